// round 4
// baseline (speedup 1.0000x reference)
#include <cuda_runtime.h>
#include <cuda_bf16.h>
#include <math.h>

// Problem constants
#define B_  4
#define L_  1024
#define D_  1024
#define DF_ 4096
#define E_  32768
#define R_  64
#define M_  (B_ * L_)
#define EPS_ 1e-6f

// ---------------------------------------------------------------------------
// Scratch
// ---------------------------------------------------------------------------
__device__ float g_hsnorm[M_ * D_];
__device__ float g_q[M_ * D_];
__device__ float g_k[M_ * D_];
__device__ float g_v[M_ * D_];
__device__ float g_o[M_ * D_];
__device__ float g_t1[M_ * D_];
__device__ float g_out[M_ * D_];
__device__ float g_h1[M_ * DF_];
__device__ float g_f[M_ * D_];
__device__ float g_score[B_ * E_];
__device__ int   g_perm[B_ * E_];
__device__ int   g_cnt[B_ * L_];
__device__ int   g_off[B_ * (L_ + 1)];

// ---------------------------------------------------------------------------
// LayerNorm helpers
// ---------------------------------------------------------------------------
__device__ __forceinline__ void row_moments(float4 v, float& mean, float& rstd,
                                            float* sh1, float* sh2) {
    float s  = v.x + v.y + v.z + v.w;
    float sq = v.x * v.x + v.y * v.y + v.z * v.z + v.w * v.w;
    #pragma unroll
    for (int o = 16; o; o >>= 1) {
        s  += __shfl_xor_sync(0xffffffffu, s, o);
        sq += __shfl_xor_sync(0xffffffffu, sq, o);
    }
    int warp = threadIdx.x >> 5, lane = threadIdx.x & 31;
    if (lane == 0) { sh1[warp] = s; sh2[warp] = sq; }
    __syncthreads();
    if (threadIdx.x < 8) {
        s = sh1[threadIdx.x]; sq = sh2[threadIdx.x];
        #pragma unroll
        for (int o = 4; o; o >>= 1) {
            s  += __shfl_xor_sync(0xffu, s, o);
            sq += __shfl_xor_sync(0xffu, sq, o);
        }
        if (threadIdx.x == 0) { sh1[0] = s; sh2[0] = sq; }
    }
    __syncthreads();
    mean = sh1[0] * (1.0f / D_);
    float var = sh2[0] * (1.0f / D_) - mean * mean;
    rstd = rsqrtf(var + EPS_);
}

__global__ void ln_kernel(const float* __restrict__ x, const float* __restrict__ g,
                          const float* __restrict__ b, float* __restrict__ y) {
    __shared__ float sh1[8], sh2[8];
    size_t row = blockIdx.x;
    int t = threadIdx.x;
    float4 v = ((const float4*)(x + row * D_))[t];
    float mean, rstd;
    row_moments(v, mean, rstd, sh1, sh2);
    float4 gv = ((const float4*)g)[t];
    float4 bv = ((const float4*)b)[t];
    float4 o;
    o.x = (v.x - mean) * rstd * gv.x + bv.x;
    o.y = (v.y - mean) * rstd * gv.y + bv.y;
    o.z = (v.z - mean) * rstd * gv.z + bv.z;
    o.w = (v.w - mean) * rstd * gv.w + bv.w;
    ((float4*)(y + row * D_))[t] = o;
}

__global__ void ln_elu_res_kernel(const float* __restrict__ x, const float* __restrict__ g,
                                  const float* __restrict__ b,
                                  const float* __restrict__ hidden,
                                  float* __restrict__ out) {
    __shared__ float sh1[8], sh2[8];
    size_t row = blockIdx.x;
    int t = threadIdx.x;
    float4 v = ((const float4*)(x + row * D_))[t];
    float mean, rstd;
    row_moments(v, mean, rstd, sh1, sh2);
    float4 gv = ((const float4*)g)[t];
    float4 bv = ((const float4*)b)[t];
    float4 hv = ((const float4*)(hidden + row * D_))[t];
    float n0 = (v.x - mean) * rstd * gv.x + bv.x;
    float n1 = (v.y - mean) * rstd * gv.y + bv.y;
    float n2 = (v.z - mean) * rstd * gv.z + bv.z;
    float n3 = (v.w - mean) * rstd * gv.w + bv.w;
    float4 o;
    o.x = hv.x + (n0 > 0.f ? n0 : expm1f(n0));
    o.y = hv.y + (n1 > 0.f ? n1 : expm1f(n1));
    o.z = hv.z + (n2 > 0.f ? n2 : expm1f(n2));
    o.w = hv.w + (n3 > 0.f ? n3 : expm1f(n3));
    ((float4*)(out + row * D_))[t] = o;
}

// ---------------------------------------------------------------------------
// TF32 tensor-core GEMM v4: 128x256 CTA tile, 64x64 warp tile, BK=16,
// 4-stage cp.async ring, one __syncthreads per k-tile, loads ahead of compute.
// ---------------------------------------------------------------------------
__device__ __forceinline__ void mma_tf32(float* c, const unsigned* a, const unsigned* b) {
    asm volatile(
        "mma.sync.aligned.m16n8k8.row.col.f32.tf32.tf32.f32 "
        "{%0,%1,%2,%3}, {%4,%5,%6,%7}, {%8,%9}, {%0,%1,%2,%3};"
        : "+f"(c[0]), "+f"(c[1]), "+f"(c[2]), "+f"(c[3])
        : "r"(a[0]), "r"(a[1]), "r"(a[2]), "r"(a[3]), "r"(b[0]), "r"(b[1]));
}

#define CP16(dst, src) \
    asm volatile("cp.async.cg.shared.global [%0], [%1], 16;\n" :: "r"(dst), "l"(src))

#define AP    20
#define BP    264
#define ASTG  (128 * AP)            // 2560 words / stage
#define BSTG  (16 * BP)             // 4224 words / stage
#define NSTAGE 4
#define GEMM_SMEM_BYTES (NSTAGE * (ASTG + BSTG) * 4)   // 108544

template <bool RELU>
__device__ __forceinline__ void gemm_body(
    unsigned* sm, const float* __restrict__ A, const float* __restrict__ Bm,
    const float* bias, const float* res, float* __restrict__ C,
    int N, int K, int bm, int bn) {
    unsigned* As = sm;                       // [NSTAGE][128][AP]
    unsigned* Bs = sm + NSTAGE * ASTG;       // [NSTAGE][16][BP]
    int tid = threadIdx.x;
    int warp = tid >> 5, lane = tid & 31;
    int g = lane >> 2, tg = lane & 3;
    int wm = (warp & 1) * 64, wn = (warp >> 1) * 64;

    int arow = tid >> 1, ahalf = (tid & 1) * 8;
    const float* aptr = A + (size_t)(bm + arow) * K + ahalf;
    unsigned a_dst = (unsigned)__cvta_generic_to_shared(As + arow * AP + ahalf);
    int brow = tid >> 4, bcg = (tid & 15) * 16;
    const float* bptr = Bm + (size_t)brow * N + bn + bcg;
    unsigned b_dst = (unsigned)__cvta_generic_to_shared(Bs + brow * BP + bcg);

    int ntiles = K >> 4;

    // Prologue: issue stages 0..NSTAGE-2
    #pragma unroll
    for (int s = 0; s < NSTAGE - 1; s++) {
        const float* ap = aptr + s * 16;
        const float* bp = bptr + (size_t)s * 16 * N;
        unsigned ad = a_dst + s * ASTG * 4;
        unsigned bd = b_dst + s * BSTG * 4;
        CP16(ad, ap); CP16(ad + 16, ap + 4);
        CP16(bd, bp); CP16(bd + 16, bp + 4);
        CP16(bd + 32, bp + 8); CP16(bd + 48, bp + 12);
        asm volatile("cp.async.commit_group;\n");
    }

    float acc[4][8][4];
    #pragma unroll
    for (int mt = 0; mt < 4; mt++)
        #pragma unroll
        for (int nt = 0; nt < 8; nt++)
            #pragma unroll
            for (int r = 0; r < 4; r++) acc[mt][nt][r] = 0.f;

    for (int kt = 0; kt < ntiles; kt++) {
        asm volatile("cp.async.wait_group %0;\n" :: "n"(NSTAGE - 2));
        __syncthreads();

        // Issue tile kt+NSTAGE-1 (writes stage (kt-1)%NSTAGE, safe post-sync).
        // Commit EVERY iteration (empty groups keep wait_group counting valid).
        int nx = kt + NSTAGE - 1;
        if (nx < ntiles) {
            int st = nx & (NSTAGE - 1);
            const float* ap = aptr + nx * 16;
            const float* bp = bptr + (size_t)nx * 16 * N;
            unsigned ad = a_dst + st * ASTG * 4;
            unsigned bd = b_dst + st * BSTG * 4;
            CP16(ad, ap); CP16(ad + 16, ap + 4);
            CP16(bd, bp); CP16(bd + 16, bp + 4);
            CP16(bd + 32, bp + 8); CP16(bd + 48, bp + 12);
        }
        asm volatile("cp.async.commit_group;\n");

        int cur = kt & (NSTAGE - 1);
        const unsigned* Ab = As + cur * ASTG;
        const unsigned* Bb = Bs + cur * BSTG;
        #pragma unroll
        for (int ks = 0; ks < 2; ks++) {
            int k0 = ks * 8;
            unsigned af[4][4], bf[8][2];
            #pragma unroll
            for (int mt = 0; mt < 4; mt++) {
                const unsigned* p = Ab + (wm + mt * 16 + g) * AP + k0 + tg;
                af[mt][0] = p[0];
                af[mt][1] = p[8 * AP];
                af[mt][2] = p[4];
                af[mt][3] = p[8 * AP + 4];
            }
            #pragma unroll
            for (int nt = 0; nt < 8; nt++) {
                const unsigned* p = Bb + (k0 + tg) * BP + wn + nt * 8 + g;
                bf[nt][0] = p[0];
                bf[nt][1] = p[4 * BP];
            }
            #pragma unroll
            for (int mt = 0; mt < 4; mt++)
                #pragma unroll
                for (int nt = 0; nt < 8; nt++)
                    mma_tf32(acc[mt][nt], af[mt], bf[nt]);
        }
    }

    // Epilogue (bias/res are uniform runtime branches)
    #pragma unroll
    for (int mt = 0; mt < 4; mt++) {
        #pragma unroll
        for (int nt = 0; nt < 8; nt++) {
            int col = bn + wn + nt * 8 + tg * 2;
            #pragma unroll
            for (int h = 0; h < 2; h++) {
                int row = bm + wm + mt * 16 + g + h * 8;
                float vx = acc[mt][nt][2 * h];
                float vy = acc[mt][nt][2 * h + 1];
                if (bias) {
                    float2 bb = *(const float2*)(bias + col);
                    vx += bb.x; vy += bb.y;
                }
                if (res) {
                    float2 rr = *(const float2*)(res + (size_t)row * N + col);
                    vx += rr.x; vy += rr.y;
                }
                if (RELU) { vx = fmaxf(vx, 0.f); vy = fmaxf(vy, 0.f); }
                *(float2*)(C + (size_t)row * N + col) = make_float2(vx, vy);
            }
        }
    }
}

template <bool RELU>
__global__ __launch_bounds__(256, 1) void mma_gemm_v4(
    const float* __restrict__ A, const float* __restrict__ Bm,
    const float* bias, const float* res, float* __restrict__ C,
    int M, int N, int K) {
    extern __shared__ unsigned sm[];
    gemm_body<RELU>(sm, A, Bm, bias, res, C, N, K,
                    blockIdx.y * 128, blockIdx.x * 256);
}

// Fused QKV: gridDim.z selects weight/bias/output. One launch, 384 CTAs.
struct QKVArgs {
    const float* Bm[3];
    const float* bias[3];
    float* C[3];
};

__global__ __launch_bounds__(256, 1) void mma_gemm_qkv(
    const float* __restrict__ A, QKVArgs args, int M, int N, int K) {
    extern __shared__ unsigned sm[];
    int z = blockIdx.z;
    gemm_body<false>(sm, A, args.Bm[z], args.bias[z], nullptr, args.C[z],
                     N, K, blockIdx.y * 128, blockIdx.x * 256);
}

// ---------------------------------------------------------------------------
// Edge scores
// ---------------------------------------------------------------------------
__global__ void score_kernel(const float* __restrict__ Q, const float* __restrict__ Km,
                             const float* __restrict__ rel_table,
                             const int* __restrict__ src, const int* __restrict__ dst,
                             const int* __restrict__ rel, float* __restrict__ score) {
    int idx = blockIdx.x * 4 + threadIdx.y;
    int b = idx >> 15;
    int lane = threadIdx.x;
    int s = src[idx], d = dst[idx], r = rel[idx];
    const float4* kr = (const float4*)(Km + ((size_t)b * L_ + s) * D_);
    const float4* qr = (const float4*)(Q + ((size_t)b * L_ + d) * D_);
    const float4* er = (const float4*)(rel_table + (size_t)r * D_);
    float acc = 0.f;
    #pragma unroll
    for (int i = 0; i < 8; i++) {
        int c = lane + 32 * i;
        float4 kv = kr[c], qv = qr[c], ev = er[c];
        acc = fmaf(kv.x + ev.x, qv.x, acc);
        acc = fmaf(kv.y + ev.y, qv.y, acc);
        acc = fmaf(kv.z + ev.z, qv.z, acc);
        acc = fmaf(kv.w + ev.w, qv.w, acc);
    }
    #pragma unroll
    for (int o = 16; o; o >>= 1) acc += __shfl_xor_sync(0xffffffffu, acc, o);
    if (lane == 0) {
        float sc = acc * 0.03125f;
        sc = fminf(fmaxf(sc, -10.f), 10.f);
        score[idx] = expf(sc);
    }
}

// ---------------------------------------------------------------------------
// Deterministic binning
// ---------------------------------------------------------------------------
__global__ void zero_cnt_kernel() {
    int i = blockIdx.x * 256 + threadIdx.x;
    if (i < B_ * L_) g_cnt[i] = 0;
}

__global__ void hist_kernel(const int* __restrict__ edge_dst) {
    int idx = blockIdx.x * 256 + threadIdx.x;
    if (idx < B_ * E_) atomicAdd(&g_cnt[(idx >> 15) * L_ + edge_dst[idx]], 1);
}

__global__ void scan_kernel() {
    int b = blockIdx.x, t = threadIdx.x;
    __shared__ int s[L_];
    int c = g_cnt[b * L_ + t];
    s[t] = c;
    __syncthreads();
    for (int off = 1; off < L_; off <<= 1) {
        int v = (t >= off) ? s[t - off] : 0;
        __syncthreads();
        s[t] += v;
        __syncthreads();
    }
    g_off[b * (L_ + 1) + t] = s[t] - c;
    if (t == L_ - 1) g_off[b * (L_ + 1) + L_] = s[t];
}

__global__ void fill_block_kernel(const int* __restrict__ edge_dst) {
    __shared__ int sd[1024];
    int b = blockIdx.x >> 7;
    int nodebase = (blockIdx.x & 127) * 8;
    int warp = threadIdx.x >> 5, lane = threadIdx.x & 31;
    int node = nodebase + warp;
    int w = g_off[b * (L_ + 1) + node];
    int* pb = g_perm + b * E_;
    const int* dv = edge_dst + b * E_;
    for (int base = 0; base < E_; base += 1024) {
        __syncthreads();
        #pragma unroll
        for (int i = 0; i < 4; i++) sd[threadIdx.x + 256 * i] = dv[base + threadIdx.x + 256 * i];
        __syncthreads();
        for (int c = 0; c < 1024; c += 32) {
            int d = sd[c + lane];
            unsigned m = __ballot_sync(0xffffffffu, d == node);
            if (d == node) pb[w + __popc(m & ((1u << lane) - 1))] = base + c + lane;
            w += __popc(m);
        }
    }
}

// ---------------------------------------------------------------------------
// Aggregation
// ---------------------------------------------------------------------------
__global__ void agg_kernel(const float* __restrict__ V, const float* __restrict__ rel_table,
                           const int* __restrict__ src, const int* __restrict__ rel,
                           const float* __restrict__ score) {
    int node = blockIdx.x, b = blockIdx.y;
    int t = threadIdx.x;
    int beg = g_off[b * (L_ + 1) + node];
    int end = g_off[b * (L_ + 1) + node + 1];
    const int* pb = g_perm + b * E_;
    float4 acc = make_float4(0.f, 0.f, 0.f, 0.f);
    float z = 0.f;
    for (int i = beg; i < end; i++) {
        int e = pb[i];
        float s = score[b * E_ + e];
        int sn = src[b * E_ + e];
        int r = rel[b * E_ + e];
        float4 vv = *(const float4*)(V + ((size_t)b * L_ + sn) * D_ + 4 * t);
        float4 ev = *(const float4*)(rel_table + (size_t)r * D_ + 4 * t);
        acc.x = fmaf(s, vv.x + ev.x, acc.x);
        acc.y = fmaf(s, vv.y + ev.y, acc.y);
        acc.z = fmaf(s, vv.z + ev.z, acc.z);
        acc.w = fmaf(s, vv.w + ev.w, acc.w);
        z += s;
    }
    float inv = 1.0f / z;
    float4 o = make_float4(acc.x * inv, acc.y * inv, acc.z * inv, acc.w * inv);
    *(float4*)(g_o + ((size_t)b * L_ + node) * D_ + 4 * t) = o;
}

// ---------------------------------------------------------------------------
// Launch
// ---------------------------------------------------------------------------
extern "C" void kernel_launch(void* const* d_in, const int* in_sizes, int n_in,
                              void* d_out, int out_size) {
    const float* hidden  = (const float*)d_in[0];
    const float* rel_tab = (const float*)d_in[1];
    const float* Wq = (const float*)d_in[2];
    const float* bq = (const float*)d_in[3];
    const float* Wk = (const float*)d_in[4];
    const float* Wv = (const float*)d_in[5];
    const float* Wo = (const float*)d_in[6];
    const float* bo = (const float*)d_in[7];
    const float* ln0g = (const float*)d_in[8];
    const float* ln0b = (const float*)d_in[9];
    const float* ln1g = (const float*)d_in[10];
    const float* ln1b = (const float*)d_in[11];
    const float* W1 = (const float*)d_in[12];
    const float* b1 = (const float*)d_in[13];
    const float* W2 = (const float*)d_in[14];
    const float* b2 = (const float*)d_in[15];
    const float* ln2g = (const float*)d_in[16];
    const float* ln2b = (const float*)d_in[17];
    const int* esrc = (const int*)d_in[18];
    const int* edst = (const int*)d_in[19];
    const int* erel = (const int*)d_in[20];
    float* out = (float*)d_out;

    float *p_hsnorm, *p_q, *p_k, *p_v, *p_o, *p_t1, *p_out, *p_h1, *p_f, *p_score;
    cudaGetSymbolAddress((void**)&p_hsnorm, g_hsnorm);
    cudaGetSymbolAddress((void**)&p_q, g_q);
    cudaGetSymbolAddress((void**)&p_k, g_k);
    cudaGetSymbolAddress((void**)&p_v, g_v);
    cudaGetSymbolAddress((void**)&p_o, g_o);
    cudaGetSymbolAddress((void**)&p_t1, g_t1);
    cudaGetSymbolAddress((void**)&p_out, g_out);
    cudaGetSymbolAddress((void**)&p_h1, g_h1);
    cudaGetSymbolAddress((void**)&p_f, g_f);
    cudaGetSymbolAddress((void**)&p_score, g_score);

    cudaFuncSetAttribute((const void*)mma_gemm_v4<false>,
                         cudaFuncAttributeMaxDynamicSharedMemorySize, GEMM_SMEM_BYTES);
    cudaFuncSetAttribute((const void*)mma_gemm_v4<true>,
                         cudaFuncAttributeMaxDynamicSharedMemorySize, GEMM_SMEM_BYTES);
    cudaFuncSetAttribute((const void*)mma_gemm_qkv,
                         cudaFuncAttributeMaxDynamicSharedMemorySize, GEMM_SMEM_BYTES);

    // 1. ln0
    ln_kernel<<<M_, 256>>>(hidden, ln0g, ln0b, p_hsnorm);

    // 2. fused Q,K,V GEMMs
    QKVArgs qkv;
    qkv.Bm[0] = Wq; qkv.Bm[1] = Wk; qkv.Bm[2] = Wv;
    qkv.bias[0] = bq; qkv.bias[1] = nullptr; qkv.bias[2] = nullptr;
    qkv.C[0] = p_q; qkv.C[1] = p_k; qkv.C[2] = p_v;
    dim3 gQKV(D_ / 256, M_ / 128, 3);
    mma_gemm_qkv<<<gQKV, 256, GEMM_SMEM_BYTES>>>(p_hsnorm, qkv, M_, D_, D_);

    // 3. edge scores
    score_kernel<<<(B_ * E_) / 4, dim3(32, 4)>>>(p_q, p_k, rel_tab, esrc, edst, erel, p_score);

    // 4. deterministic binning by dst
    zero_cnt_kernel<<<(B_ * L_) / 256, 256>>>();
    hist_kernel<<<(B_ * E_) / 256, 256>>>(edst);
    scan_kernel<<<B_, L_>>>();
    fill_block_kernel<<<512, 256>>>(edst);

    // 5. aggregation -> g_o
    agg_kernel<<<dim3(L_, B_), 256>>>(p_v, rel_tab, esrc, erel, p_score);

    // 6. t1 = hs_norm + o @ Wo + bo ; ln1 -> out
    dim3 gD(D_ / 256, M_ / 128);
    mma_gemm_v4<false><<<gD, 256, GEMM_SMEM_BYTES>>>(p_o, Wo, bo, p_hsnorm, p_t1, M_, D_, D_);
    ln_kernel<<<M_, 256>>>(p_t1, ln1g, ln1b, p_out);

    // 7. FFN
    dim3 gDF(DF_ / 256, M_ / 128);
    mma_gemm_v4<true ><<<gDF, 256, GEMM_SMEM_BYTES>>>(p_out, W1, b1, nullptr, p_h1, M_, DF_, D_);
    mma_gemm_v4<false><<<gD,  256, GEMM_SMEM_BYTES>>>(p_h1, W2, b2, p_out, p_f, M_, D_, DF_);

    // 8. final
    ln_elu_res_kernel<<<M_, 256>>>(p_f, ln2g, ln2b, hidden, out);
}

// round 5
// speedup vs baseline: 1.5439x; 1.5439x over previous
#include <cuda_runtime.h>
#include <cuda_fp16.h>
#include <math.h>

// Problem constants
#define B_  4
#define L_  1024
#define D_  1024
#define DF_ 4096
#define E_  32768
#define R_  64
#define M_  (B_ * L_)
#define EPS_ 1e-6f

// ---------------------------------------------------------------------------
// Scratch
// ---------------------------------------------------------------------------
__device__ float  g_hsnorm[M_ * D_];
__device__ __half g_hsnorm_h[M_ * D_];
__device__ float  g_q[M_ * D_];
__device__ float  g_k[M_ * D_];
__device__ float  g_v[M_ * D_];
__device__ __half g_o_h[M_ * D_];
__device__ float  g_t1[M_ * D_];
__device__ float  g_out[M_ * D_];
__device__ __half g_out_h[M_ * D_];
__device__ __half g_h1_h[M_ * DF_];
__device__ float  g_f[M_ * D_];
__device__ float  g_score[B_ * E_];
__device__ int    g_perm[B_ * E_];
__device__ int    g_cnt[B_ * L_];
__device__ int    g_off[B_ * (L_ + 1)];
// fp16 weights
__device__ __half g_wq_h[D_ * D_];
__device__ __half g_wk_h[D_ * D_];
__device__ __half g_wv_h[D_ * D_];
__device__ __half g_wo_h[D_ * D_];
__device__ __half g_w1_h[D_ * DF_];
__device__ __half g_w2_h[DF_ * D_];

// ---------------------------------------------------------------------------
// fp32 -> fp16 convert (16B out per thread)
// ---------------------------------------------------------------------------
__global__ void cvt_f2h(const float* __restrict__ x, __half* __restrict__ y, int n) {
    int i = (blockIdx.x * 256 + threadIdx.x) * 8;
    if (i >= n) return;
    float4 v0 = *(const float4*)(x + i);
    float4 v1 = *(const float4*)(x + i + 4);
    __half2 h[4];
    h[0] = __floats2half2_rn(v0.x, v0.y);
    h[1] = __floats2half2_rn(v0.z, v0.w);
    h[2] = __floats2half2_rn(v1.x, v1.y);
    h[3] = __floats2half2_rn(v1.z, v1.w);
    *(uint4*)(y + i) = *(uint4*)h;
}

// ---------------------------------------------------------------------------
// LayerNorm helpers
// ---------------------------------------------------------------------------
__device__ __forceinline__ void row_moments(float4 v, float& mean, float& rstd,
                                            float* sh1, float* sh2) {
    float s  = v.x + v.y + v.z + v.w;
    float sq = v.x * v.x + v.y * v.y + v.z * v.z + v.w * v.w;
    #pragma unroll
    for (int o = 16; o; o >>= 1) {
        s  += __shfl_xor_sync(0xffffffffu, s, o);
        sq += __shfl_xor_sync(0xffffffffu, sq, o);
    }
    int warp = threadIdx.x >> 5, lane = threadIdx.x & 31;
    if (lane == 0) { sh1[warp] = s; sh2[warp] = sq; }
    __syncthreads();
    if (threadIdx.x < 8) {
        s = sh1[threadIdx.x]; sq = sh2[threadIdx.x];
        #pragma unroll
        for (int o = 4; o; o >>= 1) {
            s  += __shfl_xor_sync(0xffu, s, o);
            sq += __shfl_xor_sync(0xffu, sq, o);
        }
        if (threadIdx.x == 0) { sh1[0] = s; sh2[0] = sq; }
    }
    __syncthreads();
    mean = sh1[0] * (1.0f / D_);
    float var = sh2[0] * (1.0f / D_) - mean * mean;
    rstd = rsqrtf(var + EPS_);
}

// LN with dual fp32 + fp16 outputs (y16 may be null)
__global__ void ln_dual_kernel(const float* __restrict__ x, const float* __restrict__ g,
                               const float* __restrict__ b, float* __restrict__ y,
                               __half* y16) {
    __shared__ float sh1[8], sh2[8];
    size_t row = blockIdx.x;
    int t = threadIdx.x;
    float4 v = ((const float4*)(x + row * D_))[t];
    float mean, rstd;
    row_moments(v, mean, rstd, sh1, sh2);
    float4 gv = ((const float4*)g)[t];
    float4 bv = ((const float4*)b)[t];
    float4 o;
    o.x = (v.x - mean) * rstd * gv.x + bv.x;
    o.y = (v.y - mean) * rstd * gv.y + bv.y;
    o.z = (v.z - mean) * rstd * gv.z + bv.z;
    o.w = (v.w - mean) * rstd * gv.w + bv.w;
    ((float4*)(y + row * D_))[t] = o;
    if (y16) {
        __half2 h0 = __floats2half2_rn(o.x, o.y);
        __half2 h1 = __floats2half2_rn(o.z, o.w);
        __half2* p = (__half2*)(y16 + row * D_);
        p[2 * t] = h0; p[2 * t + 1] = h1;
    }
}

__global__ void ln_elu_res_kernel(const float* __restrict__ x, const float* __restrict__ g,
                                  const float* __restrict__ b,
                                  const float* __restrict__ hidden,
                                  float* __restrict__ out) {
    __shared__ float sh1[8], sh2[8];
    size_t row = blockIdx.x;
    int t = threadIdx.x;
    float4 v = ((const float4*)(x + row * D_))[t];
    float mean, rstd;
    row_moments(v, mean, rstd, sh1, sh2);
    float4 gv = ((const float4*)g)[t];
    float4 bv = ((const float4*)b)[t];
    float4 hv = ((const float4*)(hidden + row * D_))[t];
    float n0 = (v.x - mean) * rstd * gv.x + bv.x;
    float n1 = (v.y - mean) * rstd * gv.y + bv.y;
    float n2 = (v.z - mean) * rstd * gv.z + bv.z;
    float n3 = (v.w - mean) * rstd * gv.w + bv.w;
    float4 o;
    o.x = hv.x + (n0 > 0.f ? n0 : expm1f(n0));
    o.y = hv.y + (n1 > 0.f ? n1 : expm1f(n1));
    o.z = hv.z + (n2 > 0.f ? n2 : expm1f(n2));
    o.w = hv.w + (n3 > 0.f ? n3 : expm1f(n3));
    ((float4*)(out + row * D_))[t] = o;
}

// ---------------------------------------------------------------------------
// FP16 tensor-core GEMM: C[M,N] = A@B (+bias)(+res)(+relu)
// CTA 128x256, 8 warps (2x4), warp 64x64, BK=32, m16n8k16, 4-stage cp.async.
// A smem row-major pitch 20 words (16 data + 4 pad) -> conflict-free LDS.32.
// B smem row-major fp16 pitch 264 (528B, ≡16 mod 128) -> conflict-free LDSM.
// ---------------------------------------------------------------------------
__device__ __forceinline__ void mma_f16(float* c, const unsigned* a, const unsigned* b) {
    asm volatile(
        "mma.sync.aligned.m16n8k16.row.col.f32.f16.f16.f32 "
        "{%0,%1,%2,%3}, {%4,%5,%6,%7}, {%8,%9}, {%0,%1,%2,%3};"
        : "+f"(c[0]), "+f"(c[1]), "+f"(c[2]), "+f"(c[3])
        : "r"(a[0]), "r"(a[1]), "r"(a[2]), "r"(a[3]), "r"(b[0]), "r"(b[1]));
}

#define CP16(dst, src) \
    asm volatile("cp.async.cg.shared.global [%0], [%1], 16;\n" :: "r"(dst), "l"(src))

#define APW   20                       // A pitch, 32-bit words (2 fp16 each)
#define ASTG  (128 * APW)              // 2560 words / stage
#define PBH   264                      // B pitch in fp16 (528 B)
#define BSTGW (32 * PBH / 2)           // 4224 words / stage
#define NSTAGE 4
#define GEMM_SMEM_BYTES (NSTAGE * (ASTG + BSTGW) * 4)   // 108544

template <bool RELU, bool OUTHALF>
__device__ __forceinline__ void gemm_body_h(
    unsigned* sm, const __half* __restrict__ A, const __half* __restrict__ Bm,
    const float* bias, const float* res, float* C32, __half* C16,
    int N, int K, int bm, int bn) {
    unsigned* As = sm;                       // [NSTAGE][128][APW]
    unsigned* Bs = sm + NSTAGE * ASTG;       // [NSTAGE][32][PBH/2]
    int tid = threadIdx.x;
    int warp = tid >> 5, lane = tid & 31;
    int g = lane >> 2, tg = lane & 3;
    int wm = (warp & 1) * 64, wn = (warp >> 1) * 64;

    // A cp.async: row 32 fp16 = 64B; each thread 32B (2 chunks)
    int arow = tid >> 1, ahalf = (tid & 1) * 16;        // fp16 units
    const __half* aptr = A + (size_t)(bm + arow) * K + ahalf;
    unsigned a_dst = (unsigned)__cvta_generic_to_shared(As + arow * APW + (tid & 1) * 8);
    // B cp.async: 32 rows x 512B; each thread 64B (4 chunks)
    int brow = tid >> 3, bc = (tid & 7) * 32;           // fp16 units
    const __half* bptr = Bm + (size_t)brow * N + bn + bc;
    unsigned b_dst = (unsigned)__cvta_generic_to_shared((__half*)Bs + brow * PBH + bc);

    // B ldmatrix lane base
    int quad = lane >> 3, j = lane & 7;
    int lrow = (quad & 1) * 8 + j;
    int lcol = wn + (quad >> 1) * 8;
    unsigned b_frag_base = (unsigned)__cvta_generic_to_shared((__half*)Bs + lrow * PBH + lcol);

    int ntiles = K >> 5;

    #pragma unroll
    for (int s = 0; s < NSTAGE - 1; s++) {
        const __half* ap = aptr + s * 32;
        const __half* bp = bptr + (size_t)s * 32 * N;
        unsigned ad = a_dst + s * ASTG * 4;
        unsigned bd = b_dst + s * BSTGW * 4;
        CP16(ad, ap); CP16(ad + 16, ap + 8);
        CP16(bd, bp); CP16(bd + 16, bp + 8);
        CP16(bd + 32, bp + 16); CP16(bd + 48, bp + 24);
        asm volatile("cp.async.commit_group;\n");
    }

    float acc[4][8][4];
    #pragma unroll
    for (int mt = 0; mt < 4; mt++)
        #pragma unroll
        for (int nt = 0; nt < 8; nt++)
            #pragma unroll
            for (int r = 0; r < 4; r++) acc[mt][nt][r] = 0.f;

    for (int kt = 0; kt < ntiles; kt++) {
        asm volatile("cp.async.wait_group %0;\n" :: "n"(NSTAGE - 2));
        __syncthreads();

        int nx = kt + NSTAGE - 1;
        if (nx < ntiles) {
            int st = nx & (NSTAGE - 1);
            const __half* ap = aptr + nx * 32;
            const __half* bp = bptr + (size_t)nx * 32 * N;
            unsigned ad = a_dst + st * ASTG * 4;
            unsigned bd = b_dst + st * BSTGW * 4;
            CP16(ad, ap); CP16(ad + 16, ap + 8);
            CP16(bd, bp); CP16(bd + 16, bp + 8);
            CP16(bd + 32, bp + 16); CP16(bd + 48, bp + 24);
        }
        asm volatile("cp.async.commit_group;\n");

        int cur = kt & (NSTAGE - 1);
        const unsigned* Ab = As + cur * ASTG;
        unsigned bsm = b_frag_base + cur * BSTGW * 4;
        #pragma unroll
        for (int ks = 0; ks < 2; ks++) {
            unsigned af[4][4];
            #pragma unroll
            for (int mt = 0; mt < 4; mt++) {
                const unsigned* p = Ab + (wm + mt * 16 + g) * APW + ks * 8 + tg;
                af[mt][0] = p[0];
                af[mt][1] = p[8 * APW];
                af[mt][2] = p[4];
                af[mt][3] = p[8 * APW + 4];
            }
            unsigned bf[8][2];
            #pragma unroll
            for (int nb = 0; nb < 4; nb++) {
                unsigned addr = bsm + ks * 16 * (PBH * 2) + nb * 32;
                asm volatile(
                    "ldmatrix.sync.aligned.m8n8.x4.trans.shared.b16 {%0,%1,%2,%3}, [%4];"
                    : "=r"(bf[2 * nb][0]), "=r"(bf[2 * nb][1]),
                      "=r"(bf[2 * nb + 1][0]), "=r"(bf[2 * nb + 1][1])
                    : "r"(addr));
            }
            #pragma unroll
            for (int mt = 0; mt < 4; mt++)
                #pragma unroll
                for (int nt = 0; nt < 8; nt++)
                    mma_f16(acc[mt][nt], af[mt], bf[nt]);
        }
    }

    // Epilogue
    #pragma unroll
    for (int mt = 0; mt < 4; mt++) {
        #pragma unroll
        for (int nt = 0; nt < 8; nt++) {
            int col = bn + wn + nt * 8 + tg * 2;
            #pragma unroll
            for (int h = 0; h < 2; h++) {
                int row = bm + wm + mt * 16 + g + h * 8;
                float vx = acc[mt][nt][2 * h];
                float vy = acc[mt][nt][2 * h + 1];
                if (bias) {
                    float2 bb = *(const float2*)(bias + col);
                    vx += bb.x; vy += bb.y;
                }
                if (res) {
                    float2 rr = *(const float2*)(res + (size_t)row * N + col);
                    vx += rr.x; vy += rr.y;
                }
                if (RELU) { vx = fmaxf(vx, 0.f); vy = fmaxf(vy, 0.f); }
                if (OUTHALF)
                    *(__half2*)(C16 + (size_t)row * N + col) = __floats2half2_rn(vx, vy);
                else
                    *(float2*)(C32 + (size_t)row * N + col) = make_float2(vx, vy);
            }
        }
    }
}

template <bool RELU, bool OUTHALF>
__global__ __launch_bounds__(256, 1) void mma_gemm_h(
    const __half* __restrict__ A, const __half* __restrict__ Bm,
    const float* bias, const float* res, float* C32, __half* C16,
    int M, int N, int K) {
    extern __shared__ unsigned sm[];
    gemm_body_h<RELU, OUTHALF>(sm, A, Bm, bias, res, C32, C16, N, K,
                               blockIdx.y * 128, blockIdx.x * 256);
}

struct QKVArgs {
    const __half* Bm[3];
    const float* bias[3];
    float* C[3];
};

__global__ __launch_bounds__(256, 1) void mma_gemm_qkv(
    const __half* __restrict__ A, QKVArgs args, int M, int N, int K) {
    extern __shared__ unsigned sm[];
    int z = blockIdx.z;
    gemm_body_h<false, false>(sm, A, args.Bm[z], args.bias[z], nullptr, args.C[z],
                              nullptr, N, K, blockIdx.y * 128, blockIdx.x * 256);
}

// ---------------------------------------------------------------------------
// Edge scores
// ---------------------------------------------------------------------------
__global__ void score_kernel(const float* __restrict__ Q, const float* __restrict__ Km,
                             const float* __restrict__ rel_table,
                             const int* __restrict__ src, const int* __restrict__ dst,
                             const int* __restrict__ rel, float* __restrict__ score) {
    int idx = blockIdx.x * 4 + threadIdx.y;
    int b = idx >> 15;
    int lane = threadIdx.x;
    int s = src[idx], d = dst[idx], r = rel[idx];
    const float4* kr = (const float4*)(Km + ((size_t)b * L_ + s) * D_);
    const float4* qr = (const float4*)(Q + ((size_t)b * L_ + d) * D_);
    const float4* er = (const float4*)(rel_table + (size_t)r * D_);
    float acc = 0.f;
    #pragma unroll
    for (int i = 0; i < 8; i++) {
        int c = lane + 32 * i;
        float4 kv = kr[c], qv = qr[c], ev = er[c];
        acc = fmaf(kv.x + ev.x, qv.x, acc);
        acc = fmaf(kv.y + ev.y, qv.y, acc);
        acc = fmaf(kv.z + ev.z, qv.z, acc);
        acc = fmaf(kv.w + ev.w, qv.w, acc);
    }
    #pragma unroll
    for (int o = 16; o; o >>= 1) acc += __shfl_xor_sync(0xffffffffu, acc, o);
    if (lane == 0) {
        float sc = acc * 0.03125f;
        sc = fminf(fmaxf(sc, -10.f), 10.f);
        score[idx] = expf(sc);
    }
}

// ---------------------------------------------------------------------------
// Deterministic binning
// ---------------------------------------------------------------------------
__global__ void zero_cnt_kernel() {
    int i = blockIdx.x * 256 + threadIdx.x;
    if (i < B_ * L_) g_cnt[i] = 0;
}

__global__ void hist_kernel(const int* __restrict__ edge_dst) {
    int idx = blockIdx.x * 256 + threadIdx.x;
    if (idx < B_ * E_) atomicAdd(&g_cnt[(idx >> 15) * L_ + edge_dst[idx]], 1);
}

__global__ void scan_kernel() {
    int b = blockIdx.x, t = threadIdx.x;
    __shared__ int s[L_];
    int c = g_cnt[b * L_ + t];
    s[t] = c;
    __syncthreads();
    for (int off = 1; off < L_; off <<= 1) {
        int v = (t >= off) ? s[t - off] : 0;
        __syncthreads();
        s[t] += v;
        __syncthreads();
    }
    g_off[b * (L_ + 1) + t] = s[t] - c;
    if (t == L_ - 1) g_off[b * (L_ + 1) + L_] = s[t];
}

__global__ void fill_block_kernel(const int* __restrict__ edge_dst) {
    __shared__ int sd[1024];
    int b = blockIdx.x >> 7;
    int nodebase = (blockIdx.x & 127) * 8;
    int warp = threadIdx.x >> 5, lane = threadIdx.x & 31;
    int node = nodebase + warp;
    int w = g_off[b * (L_ + 1) + node];
    int* pb = g_perm + b * E_;
    const int* dv = edge_dst + b * E_;
    for (int base = 0; base < E_; base += 1024) {
        __syncthreads();
        #pragma unroll
        for (int i = 0; i < 4; i++) sd[threadIdx.x + 256 * i] = dv[base + threadIdx.x + 256 * i];
        __syncthreads();
        for (int c = 0; c < 1024; c += 32) {
            int d = sd[c + lane];
            unsigned m = __ballot_sync(0xffffffffu, d == node);
            if (d == node) pb[w + __popc(m & ((1u << lane) - 1))] = base + c + lane;
            w += __popc(m);
        }
    }
}

// ---------------------------------------------------------------------------
// Aggregation -> fp16 o
// ---------------------------------------------------------------------------
__global__ void agg_kernel(const float* __restrict__ V, const float* __restrict__ rel_table,
                           const int* __restrict__ src, const int* __restrict__ rel,
                           const float* __restrict__ score) {
    int node = blockIdx.x, b = blockIdx.y;
    int t = threadIdx.x;
    int beg = g_off[b * (L_ + 1) + node];
    int end = g_off[b * (L_ + 1) + node + 1];
    const int* pb = g_perm + b * E_;
    float4 acc = make_float4(0.f, 0.f, 0.f, 0.f);
    float z = 0.f;
    for (int i = beg; i < end; i++) {
        int e = pb[i];
        float s = score[b * E_ + e];
        int sn = src[b * E_ + e];
        int r = rel[b * E_ + e];
        float4 vv = *(const float4*)(V + ((size_t)b * L_ + sn) * D_ + 4 * t);
        float4 ev = *(const float4*)(rel_table + (size_t)r * D_ + 4 * t);
        acc.x = fmaf(s, vv.x + ev.x, acc.x);
        acc.y = fmaf(s, vv.y + ev.y, acc.y);
        acc.z = fmaf(s, vv.z + ev.z, acc.z);
        acc.w = fmaf(s, vv.w + ev.w, acc.w);
        z += s;
    }
    float inv = 1.0f / z;
    __half2* dst = (__half2*)(g_o_h + ((size_t)b * L_ + node) * D_ + 4 * t);
    dst[0] = __floats2half2_rn(acc.x * inv, acc.y * inv);
    dst[1] = __floats2half2_rn(acc.z * inv, acc.w * inv);
}

// ---------------------------------------------------------------------------
// Launch
// ---------------------------------------------------------------------------
extern "C" void kernel_launch(void* const* d_in, const int* in_sizes, int n_in,
                              void* d_out, int out_size) {
    const float* hidden  = (const float*)d_in[0];
    const float* rel_tab = (const float*)d_in[1];
    const float* Wq = (const float*)d_in[2];
    const float* bq = (const float*)d_in[3];
    const float* Wk = (const float*)d_in[4];
    const float* Wv = (const float*)d_in[5];
    const float* Wo = (const float*)d_in[6];
    const float* bo = (const float*)d_in[7];
    const float* ln0g = (const float*)d_in[8];
    const float* ln0b = (const float*)d_in[9];
    const float* ln1g = (const float*)d_in[10];
    const float* ln1b = (const float*)d_in[11];
    const float* W1 = (const float*)d_in[12];
    const float* b1 = (const float*)d_in[13];
    const float* W2 = (const float*)d_in[14];
    const float* b2 = (const float*)d_in[15];
    const float* ln2g = (const float*)d_in[16];
    const float* ln2b = (const float*)d_in[17];
    const int* esrc = (const int*)d_in[18];
    const int* edst = (const int*)d_in[19];
    const int* erel = (const int*)d_in[20];
    float* out = (float*)d_out;

    float *p_hsnorm, *p_q, *p_k, *p_v, *p_t1, *p_out, *p_f, *p_score;
    __half *p_hsnorm_h, *p_o_h, *p_out_h, *p_h1_h;
    __half *p_wq_h, *p_wk_h, *p_wv_h, *p_wo_h, *p_w1_h, *p_w2_h;
    cudaGetSymbolAddress((void**)&p_hsnorm, g_hsnorm);
    cudaGetSymbolAddress((void**)&p_hsnorm_h, g_hsnorm_h);
    cudaGetSymbolAddress((void**)&p_q, g_q);
    cudaGetSymbolAddress((void**)&p_k, g_k);
    cudaGetSymbolAddress((void**)&p_v, g_v);
    cudaGetSymbolAddress((void**)&p_o_h, g_o_h);
    cudaGetSymbolAddress((void**)&p_t1, g_t1);
    cudaGetSymbolAddress((void**)&p_out, g_out);
    cudaGetSymbolAddress((void**)&p_out_h, g_out_h);
    cudaGetSymbolAddress((void**)&p_h1_h, g_h1_h);
    cudaGetSymbolAddress((void**)&p_f, g_f);
    cudaGetSymbolAddress((void**)&p_score, g_score);
    cudaGetSymbolAddress((void**)&p_wq_h, g_wq_h);
    cudaGetSymbolAddress((void**)&p_wk_h, g_wk_h);
    cudaGetSymbolAddress((void**)&p_wv_h, g_wv_h);
    cudaGetSymbolAddress((void**)&p_wo_h, g_wo_h);
    cudaGetSymbolAddress((void**)&p_w1_h, g_w1_h);
    cudaGetSymbolAddress((void**)&p_w2_h, g_w2_h);

    cudaFuncSetAttribute((const void*)mma_gemm_h<false, false>,
                         cudaFuncAttributeMaxDynamicSharedMemorySize, GEMM_SMEM_BYTES);
    cudaFuncSetAttribute((const void*)mma_gemm_h<true, true>,
                         cudaFuncAttributeMaxDynamicSharedMemorySize, GEMM_SMEM_BYTES);
    cudaFuncSetAttribute((const void*)mma_gemm_qkv,
                         cudaFuncAttributeMaxDynamicSharedMemorySize, GEMM_SMEM_BYTES);

    // 0. weight conversions (independent of everything else)
    cvt_f2h<<<(D_ * D_) / 2048, 256>>>(Wq, p_wq_h, D_ * D_);
    cvt_f2h<<<(D_ * D_) / 2048, 256>>>(Wk, p_wk_h, D_ * D_);
    cvt_f2h<<<(D_ * D_) / 2048, 256>>>(Wv, p_wv_h, D_ * D_);
    cvt_f2h<<<(D_ * D_) / 2048, 256>>>(Wo, p_wo_h, D_ * D_);
    cvt_f2h<<<(D_ * DF_) / 2048, 256>>>(W1, p_w1_h, D_ * DF_);
    cvt_f2h<<<(DF_ * D_) / 2048, 256>>>(W2, p_w2_h, DF_ * D_);

    // 1. ln0 (dual fp32 + fp16)
    ln_dual_kernel<<<M_, 256>>>(hidden, ln0g, ln0b, p_hsnorm, p_hsnorm_h);

    // 2. fused Q,K,V GEMMs
    QKVArgs qkv;
    qkv.Bm[0] = p_wq_h; qkv.Bm[1] = p_wk_h; qkv.Bm[2] = p_wv_h;
    qkv.bias[0] = bq; qkv.bias[1] = nullptr; qkv.bias[2] = nullptr;
    qkv.C[0] = p_q; qkv.C[1] = p_k; qkv.C[2] = p_v;
    dim3 gQKV(D_ / 256, M_ / 128, 3);
    mma_gemm_qkv<<<gQKV, 256, GEMM_SMEM_BYTES>>>(p_hsnorm_h, qkv, M_, D_, D_);

    // 3. edge scores
    score_kernel<<<(B_ * E_) / 4, dim3(32, 4)>>>(p_q, p_k, rel_tab, esrc, edst, erel, p_score);

    // 4. deterministic binning by dst
    zero_cnt_kernel<<<(B_ * L_) / 256, 256>>>();
    hist_kernel<<<(B_ * E_) / 256, 256>>>(edst);
    scan_kernel<<<B_, L_>>>();
    fill_block_kernel<<<512, 256>>>(edst);

    // 5. aggregation -> o_h (fp16)
    agg_kernel<<<dim3(L_, B_), 256>>>(p_v, rel_tab, esrc, erel, p_score);

    // 6. t1 = hs_norm + o @ Wo + bo ; ln1 -> out (dual)
    dim3 gD(D_ / 256, M_ / 128);
    mma_gemm_h<false, false><<<gD, 256, GEMM_SMEM_BYTES>>>(
        p_o_h, p_wo_h, bo, p_hsnorm, p_t1, nullptr, M_, D_, D_);
    ln_dual_kernel<<<M_, 256>>>(p_t1, ln1g, ln1b, p_out, p_out_h);

    // 7. FFN: h1 = relu(out @ W1 + b1) in fp16; f = out + h1 @ W2 + b2
    dim3 gDF(DF_ / 256, M_ / 128);
    mma_gemm_h<true, true><<<gDF, 256, GEMM_SMEM_BYTES>>>(
        p_out_h, p_w1_h, b1, nullptr, nullptr, p_h1_h, M_, DF_, D_);
    mma_gemm_h<false, false><<<gD, 256, GEMM_SMEM_BYTES>>>(
        p_h1_h, p_w2_h, b2, p_out, p_f, nullptr, M_, D_, DF_);

    // 8. final
    ln_elu_res_kernel<<<M_, 256>>>(p_f, ln2g, ln2b, hidden, out);
}

// round 6
// speedup vs baseline: 1.6261x; 1.0532x over previous
#include <cuda_runtime.h>
#include <cuda_fp16.h>
#include <math.h>

// Problem constants
#define B_  4
#define L_  1024
#define D_  1024
#define DF_ 4096
#define E_  32768
#define R_  64
#define M_  (B_ * L_)
#define EPS_ 1e-6f

// ---------------------------------------------------------------------------
// Scratch
// ---------------------------------------------------------------------------
__device__ float  g_hsnorm[M_ * D_];
__device__ __half g_hsnorm_h[M_ * D_];
__device__ __half g_q_h[M_ * D_];
__device__ __half g_k_h[M_ * D_];
__device__ __half g_v_h[M_ * D_];
__device__ __half g_o_h[M_ * D_];
__device__ float  g_t1[M_ * D_];
__device__ float  g_out[M_ * D_];
__device__ __half g_out_h[M_ * D_];
__device__ __half g_h1_h[M_ * DF_];
__device__ float  g_f[M_ * D_];
__device__ float  g_score[B_ * E_];
__device__ int    g_perm[B_ * E_];
__device__ int    g_cnt[B_ * L_];
__device__ int    g_off[B_ * (L_ + 1)];
// fp16 weights + tables
__device__ __half g_wq_h[D_ * D_];
__device__ __half g_wk_h[D_ * D_];
__device__ __half g_wv_h[D_ * D_];
__device__ __half g_wo_h[D_ * D_];
__device__ __half g_w1_h[D_ * DF_];
__device__ __half g_w2_h[DF_ * D_];
__device__ __half g_rel_h[R_ * D_];

// ---------------------------------------------------------------------------
// fp32 -> fp16 convert
// ---------------------------------------------------------------------------
__global__ void cvt_f2h(const float* __restrict__ x, __half* __restrict__ y, int n) {
    int i = (blockIdx.x * 256 + threadIdx.x) * 8;
    if (i >= n) return;
    float4 v0 = *(const float4*)(x + i);
    float4 v1 = *(const float4*)(x + i + 4);
    __half2 h[4];
    h[0] = __floats2half2_rn(v0.x, v0.y);
    h[1] = __floats2half2_rn(v0.z, v0.w);
    h[2] = __floats2half2_rn(v1.x, v1.y);
    h[3] = __floats2half2_rn(v1.z, v1.w);
    *(uint4*)(y + i) = *(uint4*)h;
}

// ---------------------------------------------------------------------------
// LayerNorm helpers
// ---------------------------------------------------------------------------
__device__ __forceinline__ void row_moments(float4 v, float& mean, float& rstd,
                                            float* sh1, float* sh2) {
    float s  = v.x + v.y + v.z + v.w;
    float sq = v.x * v.x + v.y * v.y + v.z * v.z + v.w * v.w;
    #pragma unroll
    for (int o = 16; o; o >>= 1) {
        s  += __shfl_xor_sync(0xffffffffu, s, o);
        sq += __shfl_xor_sync(0xffffffffu, sq, o);
    }
    int warp = threadIdx.x >> 5, lane = threadIdx.x & 31;
    if (lane == 0) { sh1[warp] = s; sh2[warp] = sq; }
    __syncthreads();
    if (threadIdx.x < 8) {
        s = sh1[threadIdx.x]; sq = sh2[threadIdx.x];
        #pragma unroll
        for (int o = 4; o; o >>= 1) {
            s  += __shfl_xor_sync(0xffu, s, o);
            sq += __shfl_xor_sync(0xffu, sq, o);
        }
        if (threadIdx.x == 0) { sh1[0] = s; sh2[0] = sq; }
    }
    __syncthreads();
    mean = sh1[0] * (1.0f / D_);
    float var = sh2[0] * (1.0f / D_) - mean * mean;
    rstd = rsqrtf(var + EPS_);
}

__global__ void ln_dual_kernel(const float* __restrict__ x, const float* __restrict__ g,
                               const float* __restrict__ b, float* __restrict__ y,
                               __half* y16) {
    __shared__ float sh1[8], sh2[8];
    size_t row = blockIdx.x;
    int t = threadIdx.x;
    float4 v = ((const float4*)(x + row * D_))[t];
    float mean, rstd;
    row_moments(v, mean, rstd, sh1, sh2);
    float4 gv = ((const float4*)g)[t];
    float4 bv = ((const float4*)b)[t];
    float4 o;
    o.x = (v.x - mean) * rstd * gv.x + bv.x;
    o.y = (v.y - mean) * rstd * gv.y + bv.y;
    o.z = (v.z - mean) * rstd * gv.z + bv.z;
    o.w = (v.w - mean) * rstd * gv.w + bv.w;
    ((float4*)(y + row * D_))[t] = o;
    if (y16) {
        __half2 h0 = __floats2half2_rn(o.x, o.y);
        __half2 h1 = __floats2half2_rn(o.z, o.w);
        __half2* p = (__half2*)(y16 + row * D_);
        p[2 * t] = h0; p[2 * t + 1] = h1;
    }
}

__global__ void ln_elu_res_kernel(const float* __restrict__ x, const float* __restrict__ g,
                                  const float* __restrict__ b,
                                  const float* __restrict__ hidden,
                                  float* __restrict__ out) {
    __shared__ float sh1[8], sh2[8];
    size_t row = blockIdx.x;
    int t = threadIdx.x;
    float4 v = ((const float4*)(x + row * D_))[t];
    float mean, rstd;
    row_moments(v, mean, rstd, sh1, sh2);
    float4 gv = ((const float4*)g)[t];
    float4 bv = ((const float4*)b)[t];
    float4 hv = ((const float4*)(hidden + row * D_))[t];
    float n0 = (v.x - mean) * rstd * gv.x + bv.x;
    float n1 = (v.y - mean) * rstd * gv.y + bv.y;
    float n2 = (v.z - mean) * rstd * gv.z + bv.z;
    float n3 = (v.w - mean) * rstd * gv.w + bv.w;
    float4 o;
    o.x = hv.x + (n0 > 0.f ? n0 : expm1f(n0));
    o.y = hv.y + (n1 > 0.f ? n1 : expm1f(n1));
    o.z = hv.z + (n2 > 0.f ? n2 : expm1f(n2));
    o.w = hv.w + (n3 > 0.f ? n3 : expm1f(n3));
    ((float4*)(out + row * D_))[t] = o;
}

// ---------------------------------------------------------------------------
// FP16 tensor-core GEMM (unchanged core from round 5)
// ---------------------------------------------------------------------------
__device__ __forceinline__ void mma_f16(float* c, const unsigned* a, const unsigned* b) {
    asm volatile(
        "mma.sync.aligned.m16n8k16.row.col.f32.f16.f16.f32 "
        "{%0,%1,%2,%3}, {%4,%5,%6,%7}, {%8,%9}, {%0,%1,%2,%3};"
        : "+f"(c[0]), "+f"(c[1]), "+f"(c[2]), "+f"(c[3])
        : "r"(a[0]), "r"(a[1]), "r"(a[2]), "r"(a[3]), "r"(b[0]), "r"(b[1]));
}

#define CP16(dst, src) \
    asm volatile("cp.async.cg.shared.global [%0], [%1], 16;\n" :: "r"(dst), "l"(src))

#define APW   20
#define ASTG  (128 * APW)
#define PBH   264
#define BSTGW (32 * PBH / 2)
#define NSTAGE 4
#define GEMM_SMEM_BYTES (NSTAGE * (ASTG + BSTGW) * 4)   // 108544

template <bool RELU, bool OUTHALF>
__device__ __forceinline__ void gemm_body_h(
    unsigned* sm, const __half* __restrict__ A, const __half* __restrict__ Bm,
    const float* bias, const float* res, float* C32, __half* C16,
    int N, int K, int bm, int bn) {
    unsigned* As = sm;
    unsigned* Bs = sm + NSTAGE * ASTG;
    int tid = threadIdx.x;
    int warp = tid >> 5, lane = tid & 31;
    int g = lane >> 2, tg = lane & 3;
    int wm = (warp & 1) * 64, wn = (warp >> 1) * 64;

    int arow = tid >> 1, ahalf = (tid & 1) * 16;
    const __half* aptr = A + (size_t)(bm + arow) * K + ahalf;
    unsigned a_dst = (unsigned)__cvta_generic_to_shared(As + arow * APW + (tid & 1) * 8);
    int brow = tid >> 3, bc = (tid & 7) * 32;
    const __half* bptr = Bm + (size_t)brow * N + bn + bc;
    unsigned b_dst = (unsigned)__cvta_generic_to_shared((__half*)Bs + brow * PBH + bc);

    int quad = lane >> 3, j = lane & 7;
    int lrow = (quad & 1) * 8 + j;
    int lcol = wn + (quad >> 1) * 8;
    unsigned b_frag_base = (unsigned)__cvta_generic_to_shared((__half*)Bs + lrow * PBH + lcol);

    int ntiles = K >> 5;

    #pragma unroll
    for (int s = 0; s < NSTAGE - 1; s++) {
        const __half* ap = aptr + s * 32;
        const __half* bp = bptr + (size_t)s * 32 * N;
        unsigned ad = a_dst + s * ASTG * 4;
        unsigned bd = b_dst + s * BSTGW * 4;
        CP16(ad, ap); CP16(ad + 16, ap + 8);
        CP16(bd, bp); CP16(bd + 16, bp + 8);
        CP16(bd + 32, bp + 16); CP16(bd + 48, bp + 24);
        asm volatile("cp.async.commit_group;\n");
    }

    float acc[4][8][4];
    #pragma unroll
    for (int mt = 0; mt < 4; mt++)
        #pragma unroll
        for (int nt = 0; nt < 8; nt++)
            #pragma unroll
            for (int r = 0; r < 4; r++) acc[mt][nt][r] = 0.f;

    for (int kt = 0; kt < ntiles; kt++) {
        asm volatile("cp.async.wait_group %0;\n" :: "n"(NSTAGE - 2));
        __syncthreads();

        int nx = kt + NSTAGE - 1;
        if (nx < ntiles) {
            int st = nx & (NSTAGE - 1);
            const __half* ap = aptr + nx * 32;
            const __half* bp = bptr + (size_t)nx * 32 * N;
            unsigned ad = a_dst + st * ASTG * 4;
            unsigned bd = b_dst + st * BSTGW * 4;
            CP16(ad, ap); CP16(ad + 16, ap + 8);
            CP16(bd, bp); CP16(bd + 16, bp + 8);
            CP16(bd + 32, bp + 16); CP16(bd + 48, bp + 24);
        }
        asm volatile("cp.async.commit_group;\n");

        int cur = kt & (NSTAGE - 1);
        const unsigned* Ab = As + cur * ASTG;
        unsigned bsm = b_frag_base + cur * BSTGW * 4;
        #pragma unroll
        for (int ks = 0; ks < 2; ks++) {
            unsigned af[4][4];
            #pragma unroll
            for (int mt = 0; mt < 4; mt++) {
                const unsigned* p = Ab + (wm + mt * 16 + g) * APW + ks * 8 + tg;
                af[mt][0] = p[0];
                af[mt][1] = p[8 * APW];
                af[mt][2] = p[4];
                af[mt][3] = p[8 * APW + 4];
            }
            unsigned bf[8][2];
            #pragma unroll
            for (int nb = 0; nb < 4; nb++) {
                unsigned addr = bsm + ks * 16 * (PBH * 2) + nb * 32;
                asm volatile(
                    "ldmatrix.sync.aligned.m8n8.x4.trans.shared.b16 {%0,%1,%2,%3}, [%4];"
                    : "=r"(bf[2 * nb][0]), "=r"(bf[2 * nb][1]),
                      "=r"(bf[2 * nb + 1][0]), "=r"(bf[2 * nb + 1][1])
                    : "r"(addr));
            }
            #pragma unroll
            for (int mt = 0; mt < 4; mt++)
                #pragma unroll
                for (int nt = 0; nt < 8; nt++)
                    mma_f16(acc[mt][nt], af[mt], bf[nt]);
        }
    }

    #pragma unroll
    for (int mt = 0; mt < 4; mt++) {
        #pragma unroll
        for (int nt = 0; nt < 8; nt++) {
            int col = bn + wn + nt * 8 + tg * 2;
            #pragma unroll
            for (int h = 0; h < 2; h++) {
                int row = bm + wm + mt * 16 + g + h * 8;
                float vx = acc[mt][nt][2 * h];
                float vy = acc[mt][nt][2 * h + 1];
                if (bias) {
                    float2 bb = *(const float2*)(bias + col);
                    vx += bb.x; vy += bb.y;
                }
                if (res) {
                    float2 rr = *(const float2*)(res + (size_t)row * N + col);
                    vx += rr.x; vy += rr.y;
                }
                if (RELU) { vx = fmaxf(vx, 0.f); vy = fmaxf(vy, 0.f); }
                if (OUTHALF)
                    *(__half2*)(C16 + (size_t)row * N + col) = __floats2half2_rn(vx, vy);
                else
                    *(float2*)(C32 + (size_t)row * N + col) = make_float2(vx, vy);
            }
        }
    }
}

template <bool RELU, bool OUTHALF>
__global__ __launch_bounds__(256, 1) void mma_gemm_h(
    const __half* __restrict__ A, const __half* __restrict__ Bm,
    const float* bias, const float* res, float* C32, __half* C16,
    int M, int N, int K) {
    extern __shared__ unsigned sm[];
    gemm_body_h<RELU, OUTHALF>(sm, A, Bm, bias, res, C32, C16, N, K,
                               blockIdx.y * 128, blockIdx.x * 256);
}

struct QKVArgs {
    const __half* Bm[3];
    const float* bias[3];
    __half* C[3];
};

__global__ __launch_bounds__(256, 1) void mma_gemm_qkv(
    const __half* __restrict__ A, QKVArgs args, int M, int N, int K) {
    extern __shared__ unsigned sm[];
    int z = blockIdx.z;
    gemm_body_h<false, true>(sm, A, args.Bm[z], args.bias[z], nullptr, nullptr,
                             args.C[z], N, K, blockIdx.y * 128, blockIdx.x * 256);
}

// ---------------------------------------------------------------------------
// Edge scores (fp16 gathers, fp32 accumulate)
// ---------------------------------------------------------------------------
__global__ void score_kernel(const __half* __restrict__ Q, const __half* __restrict__ Km,
                             const __half* __restrict__ rel_table,
                             const int* __restrict__ src, const int* __restrict__ dst,
                             const int* __restrict__ rel, float* __restrict__ score) {
    int idx = blockIdx.x * 4 + threadIdx.y;
    int b = idx >> 15;
    int lane = threadIdx.x;
    int s = src[idx], d = dst[idx], r = rel[idx];
    const __half* kr = Km + ((size_t)b * L_ + s) * D_;
    const __half* qr = Q + ((size_t)b * L_ + d) * D_;
    const __half* er = rel_table + (size_t)r * D_;
    float acc = 0.f;
    #pragma unroll
    for (int i = 0; i < 4; i++) {
        int c = (lane + 32 * i) * 8;
        uint4 kv = *(const uint4*)(kr + c);
        uint4 qv = *(const uint4*)(qr + c);
        uint4 ev = *(const uint4*)(er + c);
        const __half2* kh = (const __half2*)&kv;
        const __half2* qh = (const __half2*)&qv;
        const __half2* eh = (const __half2*)&ev;
        #pragma unroll
        for (int j = 0; j < 4; j++) {
            float2 kf = __half22float2(kh[j]);
            float2 qf = __half22float2(qh[j]);
            float2 ef = __half22float2(eh[j]);
            acc = fmaf(kf.x + ef.x, qf.x, acc);
            acc = fmaf(kf.y + ef.y, qf.y, acc);
        }
    }
    #pragma unroll
    for (int o = 16; o; o >>= 1) acc += __shfl_xor_sync(0xffffffffu, acc, o);
    if (lane == 0) {
        float sc = acc * 0.03125f;
        sc = fminf(fmaxf(sc, -10.f), 10.f);
        score[idx] = expf(sc);
    }
}

// ---------------------------------------------------------------------------
// Deterministic binning
// ---------------------------------------------------------------------------
__global__ void zero_cnt_kernel() {
    int i = blockIdx.x * 256 + threadIdx.x;
    if (i < B_ * L_) g_cnt[i] = 0;
}

__global__ void hist_kernel(const int* __restrict__ edge_dst) {
    int idx = blockIdx.x * 256 + threadIdx.x;
    if (idx < B_ * E_) atomicAdd(&g_cnt[(idx >> 15) * L_ + edge_dst[idx]], 1);
}

__global__ void scan_kernel() {
    int b = blockIdx.x, t = threadIdx.x;
    __shared__ int s[L_];
    int c = g_cnt[b * L_ + t];
    s[t] = c;
    __syncthreads();
    for (int off = 1; off < L_; off <<= 1) {
        int v = (t >= off) ? s[t - off] : 0;
        __syncthreads();
        s[t] += v;
        __syncthreads();
    }
    g_off[b * (L_ + 1) + t] = s[t] - c;
    if (t == L_ - 1) g_off[b * (L_ + 1) + L_] = s[t];
}

__global__ void fill_block_kernel(const int* __restrict__ edge_dst) {
    __shared__ int sd[1024];
    int b = blockIdx.x >> 7;
    int nodebase = (blockIdx.x & 127) * 8;
    int warp = threadIdx.x >> 5, lane = threadIdx.x & 31;
    int node = nodebase + warp;
    int w = g_off[b * (L_ + 1) + node];
    int* pb = g_perm + b * E_;
    const int* dv = edge_dst + b * E_;
    for (int base = 0; base < E_; base += 1024) {
        __syncthreads();
        #pragma unroll
        for (int i = 0; i < 4; i++) sd[threadIdx.x + 256 * i] = dv[base + threadIdx.x + 256 * i];
        __syncthreads();
        for (int c = 0; c < 1024; c += 32) {
            int d = sd[c + lane];
            unsigned m = __ballot_sync(0xffffffffu, d == node);
            if (d == node) pb[w + __popc(m & ((1u << lane) - 1))] = base + c + lane;
            w += __popc(m);
        }
    }
}

// ---------------------------------------------------------------------------
// Aggregation (fp16 gathers, fp32 accumulate) -> fp16 o
// ---------------------------------------------------------------------------
__global__ void agg_kernel(const __half* __restrict__ V, const __half* __restrict__ rel_table,
                           const int* __restrict__ src, const int* __restrict__ rel,
                           const float* __restrict__ score) {
    int node = blockIdx.x, b = blockIdx.y;
    int t = threadIdx.x;
    int beg = g_off[b * (L_ + 1) + node];
    int end = g_off[b * (L_ + 1) + node + 1];
    const int* pb = g_perm + b * E_;
    float4 acc = make_float4(0.f, 0.f, 0.f, 0.f);
    float z = 0.f;
    for (int i = beg; i < end; i++) {
        int e = pb[i];
        float s = score[b * E_ + e];
        int sn = src[b * E_ + e];
        int r = rel[b * E_ + e];
        uint2 vw = *(const uint2*)(V + ((size_t)b * L_ + sn) * D_ + 4 * t);
        uint2 ew = *(const uint2*)(rel_table + (size_t)r * D_ + 4 * t);
        const __half2* vh = (const __half2*)&vw;
        const __half2* eh = (const __half2*)&ew;
        float2 v0 = __half22float2(vh[0]), v1 = __half22float2(vh[1]);
        float2 e0 = __half22float2(eh[0]), e1 = __half22float2(eh[1]);
        acc.x = fmaf(s, v0.x + e0.x, acc.x);
        acc.y = fmaf(s, v0.y + e0.y, acc.y);
        acc.z = fmaf(s, v1.x + e1.x, acc.z);
        acc.w = fmaf(s, v1.y + e1.y, acc.w);
        z += s;
    }
    float inv = 1.0f / z;
    __half2* dst = (__half2*)(g_o_h + ((size_t)b * L_ + node) * D_ + 4 * t);
    dst[0] = __floats2half2_rn(acc.x * inv, acc.y * inv);
    dst[1] = __floats2half2_rn(acc.z * inv, acc.w * inv);
}

// ---------------------------------------------------------------------------
// Launch
// ---------------------------------------------------------------------------
extern "C" void kernel_launch(void* const* d_in, const int* in_sizes, int n_in,
                              void* d_out, int out_size) {
    const float* hidden  = (const float*)d_in[0];
    const float* rel_tab = (const float*)d_in[1];
    const float* Wq = (const float*)d_in[2];
    const float* bq = (const float*)d_in[3];
    const float* Wk = (const float*)d_in[4];
    const float* Wv = (const float*)d_in[5];
    const float* Wo = (const float*)d_in[6];
    const float* bo = (const float*)d_in[7];
    const float* ln0g = (const float*)d_in[8];
    const float* ln0b = (const float*)d_in[9];
    const float* ln1g = (const float*)d_in[10];
    const float* ln1b = (const float*)d_in[11];
    const float* W1 = (const float*)d_in[12];
    const float* b1 = (const float*)d_in[13];
    const float* W2 = (const float*)d_in[14];
    const float* b2 = (const float*)d_in[15];
    const float* ln2g = (const float*)d_in[16];
    const float* ln2b = (const float*)d_in[17];
    const int* esrc = (const int*)d_in[18];
    const int* edst = (const int*)d_in[19];
    const int* erel = (const int*)d_in[20];
    float* out = (float*)d_out;

    float *p_hsnorm, *p_t1, *p_out, *p_f, *p_score;
    __half *p_hsnorm_h, *p_q_h, *p_k_h, *p_v_h, *p_o_h, *p_out_h, *p_h1_h;
    __half *p_wq_h, *p_wk_h, *p_wv_h, *p_wo_h, *p_w1_h, *p_w2_h, *p_rel_h;
    cudaGetSymbolAddress((void**)&p_hsnorm, g_hsnorm);
    cudaGetSymbolAddress((void**)&p_hsnorm_h, g_hsnorm_h);
    cudaGetSymbolAddress((void**)&p_q_h, g_q_h);
    cudaGetSymbolAddress((void**)&p_k_h, g_k_h);
    cudaGetSymbolAddress((void**)&p_v_h, g_v_h);
    cudaGetSymbolAddress((void**)&p_o_h, g_o_h);
    cudaGetSymbolAddress((void**)&p_t1, g_t1);
    cudaGetSymbolAddress((void**)&p_out, g_out);
    cudaGetSymbolAddress((void**)&p_out_h, g_out_h);
    cudaGetSymbolAddress((void**)&p_h1_h, g_h1_h);
    cudaGetSymbolAddress((void**)&p_f, g_f);
    cudaGetSymbolAddress((void**)&p_score, g_score);
    cudaGetSymbolAddress((void**)&p_wq_h, g_wq_h);
    cudaGetSymbolAddress((void**)&p_wk_h, g_wk_h);
    cudaGetSymbolAddress((void**)&p_wv_h, g_wv_h);
    cudaGetSymbolAddress((void**)&p_wo_h, g_wo_h);
    cudaGetSymbolAddress((void**)&p_w1_h, g_w1_h);
    cudaGetSymbolAddress((void**)&p_w2_h, g_w2_h);
    cudaGetSymbolAddress((void**)&p_rel_h, g_rel_h);

    cudaFuncSetAttribute((const void*)mma_gemm_h<false, false>,
                         cudaFuncAttributeMaxDynamicSharedMemorySize, GEMM_SMEM_BYTES);
    cudaFuncSetAttribute((const void*)mma_gemm_h<true, true>,
                         cudaFuncAttributeMaxDynamicSharedMemorySize, GEMM_SMEM_BYTES);
    cudaFuncSetAttribute((const void*)mma_gemm_qkv,
                         cudaFuncAttributeMaxDynamicSharedMemorySize, GEMM_SMEM_BYTES);

    // 0. weight + rel-table conversions
    cvt_f2h<<<(D_ * D_) / 2048, 256>>>(Wq, p_wq_h, D_ * D_);
    cvt_f2h<<<(D_ * D_) / 2048, 256>>>(Wk, p_wk_h, D_ * D_);
    cvt_f2h<<<(D_ * D_) / 2048, 256>>>(Wv, p_wv_h, D_ * D_);
    cvt_f2h<<<(D_ * D_) / 2048, 256>>>(Wo, p_wo_h, D_ * D_);
    cvt_f2h<<<(D_ * DF_) / 2048, 256>>>(W1, p_w1_h, D_ * DF_);
    cvt_f2h<<<(DF_ * D_) / 2048, 256>>>(W2, p_w2_h, DF_ * D_);
    cvt_f2h<<<(R_ * D_) / 2048, 256>>>(rel_tab, p_rel_h, R_ * D_);

    // 1. ln0
    ln_dual_kernel<<<M_, 256>>>(hidden, ln0g, ln0b, p_hsnorm, p_hsnorm_h);

    // 2. fused Q,K,V GEMMs -> fp16 outputs
    QKVArgs qkv;
    qkv.Bm[0] = p_wq_h; qkv.Bm[1] = p_wk_h; qkv.Bm[2] = p_wv_h;
    qkv.bias[0] = bq; qkv.bias[1] = nullptr; qkv.bias[2] = nullptr;
    qkv.C[0] = p_q_h; qkv.C[1] = p_k_h; qkv.C[2] = p_v_h;
    dim3 gQKV(D_ / 256, M_ / 128, 3);
    mma_gemm_qkv<<<gQKV, 256, GEMM_SMEM_BYTES>>>(p_hsnorm_h, qkv, M_, D_, D_);

    // 3. edge scores (fp16 gathers)
    score_kernel<<<(B_ * E_) / 4, dim3(32, 4)>>>(p_q_h, p_k_h, p_rel_h, esrc, edst, erel, p_score);

    // 4. deterministic binning by dst
    zero_cnt_kernel<<<(B_ * L_) / 256, 256>>>();
    hist_kernel<<<(B_ * E_) / 256, 256>>>(edst);
    scan_kernel<<<B_, L_>>>();
    fill_block_kernel<<<512, 256>>>(edst);

    // 5. aggregation -> o_h (fp16)
    agg_kernel<<<dim3(L_, B_), 256>>>(p_v_h, p_rel_h, esrc, erel, p_score);

    // 6. t1 = hs_norm + o @ Wo + bo ; ln1 -> out (dual)
    dim3 gD(D_ / 256, M_ / 128);
    mma_gemm_h<false, false><<<gD, 256, GEMM_SMEM_BYTES>>>(
        p_o_h, p_wo_h, bo, p_hsnorm, p_t1, nullptr, M_, D_, D_);
    ln_dual_kernel<<<M_, 256>>>(p_t1, ln1g, ln1b, p_out, p_out_h);

    // 7. FFN
    dim3 gDF(DF_ / 256, M_ / 128);
    mma_gemm_h<true, true><<<gDF, 256, GEMM_SMEM_BYTES>>>(
        p_out_h, p_w1_h, b1, nullptr, nullptr, p_h1_h, M_, DF_, D_);
    mma_gemm_h<false, false><<<gD, 256, GEMM_SMEM_BYTES>>>(
        p_h1_h, p_w2_h, b2, p_out, p_f, nullptr, M_, D_, DF_);

    // 8. final
    ln_elu_res_kernel<<<M_, 256>>>(p_f, ln2g, ln2b, hidden, out);
}

// round 7
// speedup vs baseline: 1.8701x; 1.1500x over previous
#include <cuda_runtime.h>
#include <cuda_fp16.h>
#include <math.h>

// Problem constants
#define B_  4
#define L_  1024
#define D_  1024
#define DF_ 4096
#define E_  32768
#define R_  64
#define M_  (B_ * L_)
#define EPS_ 1e-6f

// ---------------------------------------------------------------------------
// Scratch
// ---------------------------------------------------------------------------
__device__ float  g_hsnorm[M_ * D_];
__device__ __half g_hsnorm_h[M_ * D_];
__device__ __half g_q_h[M_ * D_];
__device__ __half g_k_h[M_ * D_];
__device__ __half g_v_h[M_ * D_];
__device__ __half g_o_h[M_ * D_];
__device__ float  g_t1[M_ * D_];
__device__ float  g_out[M_ * D_];
__device__ __half g_out_h[M_ * D_];
__device__ __half g_h1_h[M_ * DF_];
__device__ float  g_f[M_ * D_];
__device__ float  g_score[B_ * E_];
__device__ int    g_perm[B_ * E_];
__device__ int    g_cnt[B_ * L_];
__device__ int    g_off[B_ * (L_ + 1)];
// fp16 weights + tables
__device__ __half g_wq_h[D_ * D_];
__device__ __half g_wk_h[D_ * D_];
__device__ __half g_wv_h[D_ * D_];
__device__ __half g_wo_h[D_ * D_];
__device__ __half g_w1_h[D_ * DF_];
__device__ __half g_w2_h[DF_ * D_];
__device__ __half g_rel_h[R_ * D_];

// ---------------------------------------------------------------------------
// Batched fp32 -> fp16 convert: 7 segments, one launch
// ---------------------------------------------------------------------------
#define NSEG 7
struct CvtArgs {
    const float* src[NSEG];
    __half* dst[NSEG];
    int n[NSEG];
    int cum[NSEG];   // cumulative start block of each segment
};

__global__ void cvt_f2h_multi(CvtArgs a) {
    int blk = blockIdx.x;
    int seg = 0;
    #pragma unroll
    for (int i = 1; i < NSEG; i++) if (blk >= a.cum[i]) seg = i;
    int i = ((blk - a.cum[seg]) * 256 + threadIdx.x) * 8;
    if (i >= a.n[seg]) return;
    const float* x = a.src[seg];
    float4 v0 = *(const float4*)(x + i);
    float4 v1 = *(const float4*)(x + i + 4);
    __half2 h[4];
    h[0] = __floats2half2_rn(v0.x, v0.y);
    h[1] = __floats2half2_rn(v0.z, v0.w);
    h[2] = __floats2half2_rn(v1.x, v1.y);
    h[3] = __floats2half2_rn(v1.z, v1.w);
    *(uint4*)(a.dst[seg] + i) = *(uint4*)h;
}

// ---------------------------------------------------------------------------
// LayerNorm helpers
// ---------------------------------------------------------------------------
__device__ __forceinline__ void row_moments(float4 v, float& mean, float& rstd,
                                            float* sh1, float* sh2) {
    float s  = v.x + v.y + v.z + v.w;
    float sq = v.x * v.x + v.y * v.y + v.z * v.z + v.w * v.w;
    #pragma unroll
    for (int o = 16; o; o >>= 1) {
        s  += __shfl_xor_sync(0xffffffffu, s, o);
        sq += __shfl_xor_sync(0xffffffffu, sq, o);
    }
    int warp = threadIdx.x >> 5, lane = threadIdx.x & 31;
    if (lane == 0) { sh1[warp] = s; sh2[warp] = sq; }
    __syncthreads();
    if (threadIdx.x < 8) {
        s = sh1[threadIdx.x]; sq = sh2[threadIdx.x];
        #pragma unroll
        for (int o = 4; o; o >>= 1) {
            s  += __shfl_xor_sync(0xffu, s, o);
            sq += __shfl_xor_sync(0xffu, sq, o);
        }
        if (threadIdx.x == 0) { sh1[0] = s; sh2[0] = sq; }
    }
    __syncthreads();
    mean = sh1[0] * (1.0f / D_);
    float var = sh2[0] * (1.0f / D_) - mean * mean;
    rstd = rsqrtf(var + EPS_);
}

__global__ void ln_dual_kernel(const float* __restrict__ x, const float* __restrict__ g,
                               const float* __restrict__ b, float* __restrict__ y,
                               __half* y16) {
    __shared__ float sh1[8], sh2[8];
    size_t row = blockIdx.x;
    int t = threadIdx.x;
    float4 v = ((const float4*)(x + row * D_))[t];
    float mean, rstd;
    row_moments(v, mean, rstd, sh1, sh2);
    float4 gv = ((const float4*)g)[t];
    float4 bv = ((const float4*)b)[t];
    float4 o;
    o.x = (v.x - mean) * rstd * gv.x + bv.x;
    o.y = (v.y - mean) * rstd * gv.y + bv.y;
    o.z = (v.z - mean) * rstd * gv.z + bv.z;
    o.w = (v.w - mean) * rstd * gv.w + bv.w;
    ((float4*)(y + row * D_))[t] = o;
    if (y16) {
        __half2 h0 = __floats2half2_rn(o.x, o.y);
        __half2 h1 = __floats2half2_rn(o.z, o.w);
        __half2* p = (__half2*)(y16 + row * D_);
        p[2 * t] = h0; p[2 * t + 1] = h1;
    }
}

__global__ void ln_elu_res_kernel(const float* __restrict__ x, const float* __restrict__ g,
                                  const float* __restrict__ b,
                                  const float* __restrict__ hidden,
                                  float* __restrict__ out) {
    __shared__ float sh1[8], sh2[8];
    size_t row = blockIdx.x;
    int t = threadIdx.x;
    float4 v = ((const float4*)(x + row * D_))[t];
    float mean, rstd;
    row_moments(v, mean, rstd, sh1, sh2);
    float4 gv = ((const float4*)g)[t];
    float4 bv = ((const float4*)b)[t];
    float4 hv = ((const float4*)(hidden + row * D_))[t];
    float n0 = (v.x - mean) * rstd * gv.x + bv.x;
    float n1 = (v.y - mean) * rstd * gv.y + bv.y;
    float n2 = (v.z - mean) * rstd * gv.z + bv.z;
    float n3 = (v.w - mean) * rstd * gv.w + bv.w;
    float4 o;
    o.x = hv.x + (n0 > 0.f ? n0 : expm1f(n0));
    o.y = hv.y + (n1 > 0.f ? n1 : expm1f(n1));
    o.z = hv.z + (n2 > 0.f ? n2 : expm1f(n2));
    o.w = hv.w + (n3 > 0.f ? n3 : expm1f(n3));
    ((float4*)(out + row * D_))[t] = o;
}

// ---------------------------------------------------------------------------
// FP16 tensor-core GEMM v6: CTA 128x128, 8 warps (2x4), warp tile 64x32,
// BK=32, 3-stage cp.async, __launch_bounds__(256,2) -> 2 CTAs/SM.
// ---------------------------------------------------------------------------
__device__ __forceinline__ void mma_f16(float* c, const unsigned* a, const unsigned* b) {
    asm volatile(
        "mma.sync.aligned.m16n8k16.row.col.f32.f16.f16.f32 "
        "{%0,%1,%2,%3}, {%4,%5,%6,%7}, {%8,%9}, {%0,%1,%2,%3};"
        : "+f"(c[0]), "+f"(c[1]), "+f"(c[2]), "+f"(c[3])
        : "r"(a[0]), "r"(a[1]), "r"(a[2]), "r"(a[3]), "r"(b[0]), "r"(b[1]));
}

#define CP16(dst, src) \
    asm volatile("cp.async.cg.shared.global [%0], [%1], 16;\n" :: "r"(dst), "l"(src))

#define APW   20                     // A pitch, 32-bit words
#define ASTG  (128 * APW)            // 2560 words / stage
#define PBHN  136                    // B pitch in fp16 (272 B, ≡16 mod 128)
#define BSTGW (32 * PBHN / 2)        // 2176 words / stage
#define NSTAGE 3
#define GEMM_SMEM_BYTES (NSTAGE * (ASTG + BSTGW) * 4)   // 56832

template <bool RELU, bool OUTHALF>
__device__ __forceinline__ void gemm_body_h(
    unsigned* sm, const __half* __restrict__ A, const __half* __restrict__ Bm,
    const float* bias, const float* res, float* C32, __half* C16,
    int N, int K, int bm, int bn) {
    unsigned* As = sm;
    unsigned* Bs = sm + NSTAGE * ASTG;
    int tid = threadIdx.x;
    int warp = tid >> 5, lane = tid & 31;
    int g = lane >> 2, tg = lane & 3;
    int wm = (warp & 1) * 64, wn = (warp >> 1) * 32;

    // A cp.async: 128 rows x 64B; per thread 32B (2 chunks)
    int arow = tid >> 1;
    const __half* aptr = A + (size_t)(bm + arow) * K + (tid & 1) * 16;
    unsigned a_dst = (unsigned)__cvta_generic_to_shared(As + arow * APW + (tid & 1) * 8);
    // B cp.async: 32 rows x 256B; per thread 32B (2 chunks)
    int brow = tid >> 3, bc = (tid & 7) * 16;
    const __half* bptr = Bm + (size_t)brow * N + bn + bc;
    unsigned b_dst = (unsigned)__cvta_generic_to_shared((__half*)Bs + brow * PBHN + bc);

    // B ldmatrix lane base
    int quad = lane >> 3, j = lane & 7;
    int lrow = (quad & 1) * 8 + j;
    int lcol = wn + (quad >> 1) * 8;
    unsigned b_frag_base = (unsigned)__cvta_generic_to_shared((__half*)Bs + lrow * PBHN + lcol);

    int ntiles = K >> 5;

    #pragma unroll
    for (int s = 0; s < NSTAGE - 1; s++) {
        const __half* ap = aptr + s * 32;
        const __half* bp = bptr + (size_t)s * 32 * N;
        unsigned ad = a_dst + s * ASTG * 4;
        unsigned bd = b_dst + s * BSTGW * 4;
        CP16(ad, ap); CP16(ad + 16, ap + 8);
        CP16(bd, bp); CP16(bd + 16, bp + 8);
        asm volatile("cp.async.commit_group;\n");
    }

    float acc[4][4][4];
    #pragma unroll
    for (int mt = 0; mt < 4; mt++)
        #pragma unroll
        for (int nt = 0; nt < 4; nt++)
            #pragma unroll
            for (int r = 0; r < 4; r++) acc[mt][nt][r] = 0.f;

    for (int kt = 0; kt < ntiles; kt++) {
        asm volatile("cp.async.wait_group %0;\n" :: "n"(NSTAGE - 2));
        __syncthreads();

        int nx = kt + NSTAGE - 1;
        if (nx < ntiles) {
            int st = nx % NSTAGE;
            const __half* ap = aptr + nx * 32;
            const __half* bp = bptr + (size_t)nx * 32 * N;
            unsigned ad = a_dst + st * ASTG * 4;
            unsigned bd = b_dst + st * BSTGW * 4;
            CP16(ad, ap); CP16(ad + 16, ap + 8);
            CP16(bd, bp); CP16(bd + 16, bp + 8);
        }
        asm volatile("cp.async.commit_group;\n");

        int cur = kt % NSTAGE;
        const unsigned* Ab = As + cur * ASTG;
        unsigned bsm = b_frag_base + cur * BSTGW * 4;
        #pragma unroll
        for (int ks = 0; ks < 2; ks++) {
            unsigned af[4][4];
            #pragma unroll
            for (int mt = 0; mt < 4; mt++) {
                const unsigned* p = Ab + (wm + mt * 16 + g) * APW + ks * 8 + tg;
                af[mt][0] = p[0];
                af[mt][1] = p[8 * APW];
                af[mt][2] = p[4];
                af[mt][3] = p[8 * APW + 4];
            }
            unsigned bf[4][2];
            #pragma unroll
            for (int nb = 0; nb < 2; nb++) {
                unsigned addr = bsm + ks * 16 * (PBHN * 2) + nb * 32;
                asm volatile(
                    "ldmatrix.sync.aligned.m8n8.x4.trans.shared.b16 {%0,%1,%2,%3}, [%4];"
                    : "=r"(bf[2 * nb][0]), "=r"(bf[2 * nb][1]),
                      "=r"(bf[2 * nb + 1][0]), "=r"(bf[2 * nb + 1][1])
                    : "r"(addr));
            }
            #pragma unroll
            for (int mt = 0; mt < 4; mt++)
                #pragma unroll
                for (int nt = 0; nt < 4; nt++)
                    mma_f16(acc[mt][nt], af[mt], bf[nt]);
        }
    }

    #pragma unroll
    for (int mt = 0; mt < 4; mt++) {
        #pragma unroll
        for (int nt = 0; nt < 4; nt++) {
            int col = bn + wn + nt * 8 + tg * 2;
            #pragma unroll
            for (int h = 0; h < 2; h++) {
                int row = bm + wm + mt * 16 + g + h * 8;
                float vx = acc[mt][nt][2 * h];
                float vy = acc[mt][nt][2 * h + 1];
                if (bias) {
                    float2 bb = *(const float2*)(bias + col);
                    vx += bb.x; vy += bb.y;
                }
                if (res) {
                    float2 rr = *(const float2*)(res + (size_t)row * N + col);
                    vx += rr.x; vy += rr.y;
                }
                if (RELU) { vx = fmaxf(vx, 0.f); vy = fmaxf(vy, 0.f); }
                if (OUTHALF)
                    *(__half2*)(C16 + (size_t)row * N + col) = __floats2half2_rn(vx, vy);
                else
                    *(float2*)(C32 + (size_t)row * N + col) = make_float2(vx, vy);
            }
        }
    }
}

template <bool RELU, bool OUTHALF>
__global__ __launch_bounds__(256, 2) void mma_gemm_h(
    const __half* __restrict__ A, const __half* __restrict__ Bm,
    const float* bias, const float* res, float* C32, __half* C16,
    int M, int N, int K) {
    extern __shared__ unsigned sm[];
    gemm_body_h<RELU, OUTHALF>(sm, A, Bm, bias, res, C32, C16, N, K,
                               blockIdx.y * 128, blockIdx.x * 128);
}

struct QKVArgs {
    const __half* Bm[3];
    const float* bias[3];
    __half* C[3];
};

__global__ __launch_bounds__(256, 2) void mma_gemm_qkv(
    const __half* __restrict__ A, QKVArgs args, int M, int N, int K) {
    extern __shared__ unsigned sm[];
    int z = blockIdx.z;
    gemm_body_h<false, true>(sm, A, args.Bm[z], args.bias[z], nullptr, nullptr,
                             args.C[z], N, K, blockIdx.y * 128, blockIdx.x * 128);
}

// ---------------------------------------------------------------------------
// Edge scores (fp16 gathers, fp32 accumulate)
// ---------------------------------------------------------------------------
__global__ void score_kernel(const __half* __restrict__ Q, const __half* __restrict__ Km,
                             const __half* __restrict__ rel_table,
                             const int* __restrict__ src, const int* __restrict__ dst,
                             const int* __restrict__ rel, float* __restrict__ score) {
    int idx = blockIdx.x * 4 + threadIdx.y;
    int b = idx >> 15;
    int lane = threadIdx.x;
    int s = src[idx], d = dst[idx], r = rel[idx];
    const __half* kr = Km + ((size_t)b * L_ + s) * D_;
    const __half* qr = Q + ((size_t)b * L_ + d) * D_;
    const __half* er = rel_table + (size_t)r * D_;
    float acc = 0.f;
    #pragma unroll
    for (int i = 0; i < 4; i++) {
        int c = (lane + 32 * i) * 8;
        uint4 kv = *(const uint4*)(kr + c);
        uint4 qv = *(const uint4*)(qr + c);
        uint4 ev = *(const uint4*)(er + c);
        const __half2* kh = (const __half2*)&kv;
        const __half2* qh = (const __half2*)&qv;
        const __half2* eh = (const __half2*)&ev;
        #pragma unroll
        for (int j = 0; j < 4; j++) {
            float2 kf = __half22float2(kh[j]);
            float2 qf = __half22float2(qh[j]);
            float2 ef = __half22float2(eh[j]);
            acc = fmaf(kf.x + ef.x, qf.x, acc);
            acc = fmaf(kf.y + ef.y, qf.y, acc);
        }
    }
    #pragma unroll
    for (int o = 16; o; o >>= 1) acc += __shfl_xor_sync(0xffffffffu, acc, o);
    if (lane == 0) {
        float sc = acc * 0.03125f;
        sc = fminf(fmaxf(sc, -10.f), 10.f);
        score[idx] = expf(sc);
    }
}

// ---------------------------------------------------------------------------
// Deterministic binning
// ---------------------------------------------------------------------------
__global__ void zero_cnt_kernel() {
    int i = blockIdx.x * 256 + threadIdx.x;
    if (i < B_ * L_) g_cnt[i] = 0;
}

__global__ void hist_kernel(const int* __restrict__ edge_dst) {
    int idx = blockIdx.x * 256 + threadIdx.x;
    if (idx < B_ * E_) atomicAdd(&g_cnt[(idx >> 15) * L_ + edge_dst[idx]], 1);
}

__global__ void scan_kernel() {
    int b = blockIdx.x, t = threadIdx.x;
    __shared__ int s[L_];
    int c = g_cnt[b * L_ + t];
    s[t] = c;
    __syncthreads();
    for (int off = 1; off < L_; off <<= 1) {
        int v = (t >= off) ? s[t - off] : 0;
        __syncthreads();
        s[t] += v;
        __syncthreads();
    }
    g_off[b * (L_ + 1) + t] = s[t] - c;
    if (t == L_ - 1) g_off[b * (L_ + 1) + L_] = s[t];
}

__global__ void fill_block_kernel(const int* __restrict__ edge_dst) {
    __shared__ int sd[1024];
    int b = blockIdx.x >> 7;
    int nodebase = (blockIdx.x & 127) * 8;
    int warp = threadIdx.x >> 5, lane = threadIdx.x & 31;
    int node = nodebase + warp;
    int w = g_off[b * (L_ + 1) + node];
    int* pb = g_perm + b * E_;
    const int* dv = edge_dst + b * E_;
    for (int base = 0; base < E_; base += 1024) {
        __syncthreads();
        #pragma unroll
        for (int i = 0; i < 4; i++) sd[threadIdx.x + 256 * i] = dv[base + threadIdx.x + 256 * i];
        __syncthreads();
        for (int c = 0; c < 1024; c += 32) {
            int d = sd[c + lane];
            unsigned m = __ballot_sync(0xffffffffu, d == node);
            if (d == node) pb[w + __popc(m & ((1u << lane) - 1))] = base + c + lane;
            w += __popc(m);
        }
    }
}

// ---------------------------------------------------------------------------
// Aggregation (fp16 gathers, fp32 accumulate) -> fp16 o
// ---------------------------------------------------------------------------
__global__ void agg_kernel(const __half* __restrict__ V, const __half* __restrict__ rel_table,
                           const int* __restrict__ src, const int* __restrict__ rel,
                           const float* __restrict__ score) {
    int node = blockIdx.x, b = blockIdx.y;
    int t = threadIdx.x;
    int beg = g_off[b * (L_ + 1) + node];
    int end = g_off[b * (L_ + 1) + node + 1];
    const int* pb = g_perm + b * E_;
    float4 acc = make_float4(0.f, 0.f, 0.f, 0.f);
    float z = 0.f;
    for (int i = beg; i < end; i++) {
        int e = pb[i];
        float s = score[b * E_ + e];
        int sn = src[b * E_ + e];
        int r = rel[b * E_ + e];
        uint2 vw = *(const uint2*)(V + ((size_t)b * L_ + sn) * D_ + 4 * t);
        uint2 ew = *(const uint2*)(rel_table + (size_t)r * D_ + 4 * t);
        const __half2* vh = (const __half2*)&vw;
        const __half2* eh = (const __half2*)&ew;
        float2 v0 = __half22float2(vh[0]), v1 = __half22float2(vh[1]);
        float2 e0 = __half22float2(eh[0]), e1 = __half22float2(eh[1]);
        acc.x = fmaf(s, v0.x + e0.x, acc.x);
        acc.y = fmaf(s, v0.y + e0.y, acc.y);
        acc.z = fmaf(s, v1.x + e1.x, acc.z);
        acc.w = fmaf(s, v1.y + e1.y, acc.w);
        z += s;
    }
    float inv = 1.0f / z;
    __half2* dst = (__half2*)(g_o_h + ((size_t)b * L_ + node) * D_ + 4 * t);
    dst[0] = __floats2half2_rn(acc.x * inv, acc.y * inv);
    dst[1] = __floats2half2_rn(acc.z * inv, acc.w * inv);
}

// ---------------------------------------------------------------------------
// Launch
// ---------------------------------------------------------------------------
extern "C" void kernel_launch(void* const* d_in, const int* in_sizes, int n_in,
                              void* d_out, int out_size) {
    const float* hidden  = (const float*)d_in[0];
    const float* rel_tab = (const float*)d_in[1];
    const float* Wq = (const float*)d_in[2];
    const float* bq = (const float*)d_in[3];
    const float* Wk = (const float*)d_in[4];
    const float* Wv = (const float*)d_in[5];
    const float* Wo = (const float*)d_in[6];
    const float* bo = (const float*)d_in[7];
    const float* ln0g = (const float*)d_in[8];
    const float* ln0b = (const float*)d_in[9];
    const float* ln1g = (const float*)d_in[10];
    const float* ln1b = (const float*)d_in[11];
    const float* W1 = (const float*)d_in[12];
    const float* b1 = (const float*)d_in[13];
    const float* W2 = (const float*)d_in[14];
    const float* b2 = (const float*)d_in[15];
    const float* ln2g = (const float*)d_in[16];
    const float* ln2b = (const float*)d_in[17];
    const int* esrc = (const int*)d_in[18];
    const int* edst = (const int*)d_in[19];
    const int* erel = (const int*)d_in[20];
    float* out = (float*)d_out;

    float *p_hsnorm, *p_t1, *p_out, *p_f, *p_score;
    __half *p_hsnorm_h, *p_q_h, *p_k_h, *p_v_h, *p_o_h, *p_out_h, *p_h1_h;
    __half *p_wq_h, *p_wk_h, *p_wv_h, *p_wo_h, *p_w1_h, *p_w2_h, *p_rel_h;
    cudaGetSymbolAddress((void**)&p_hsnorm, g_hsnorm);
    cudaGetSymbolAddress((void**)&p_hsnorm_h, g_hsnorm_h);
    cudaGetSymbolAddress((void**)&p_q_h, g_q_h);
    cudaGetSymbolAddress((void**)&p_k_h, g_k_h);
    cudaGetSymbolAddress((void**)&p_v_h, g_v_h);
    cudaGetSymbolAddress((void**)&p_o_h, g_o_h);
    cudaGetSymbolAddress((void**)&p_t1, g_t1);
    cudaGetSymbolAddress((void**)&p_out, g_out);
    cudaGetSymbolAddress((void**)&p_out_h, g_out_h);
    cudaGetSymbolAddress((void**)&p_h1_h, g_h1_h);
    cudaGetSymbolAddress((void**)&p_f, g_f);
    cudaGetSymbolAddress((void**)&p_score, g_score);
    cudaGetSymbolAddress((void**)&p_wq_h, g_wq_h);
    cudaGetSymbolAddress((void**)&p_wk_h, g_wk_h);
    cudaGetSymbolAddress((void**)&p_wv_h, g_wv_h);
    cudaGetSymbolAddress((void**)&p_wo_h, g_wo_h);
    cudaGetSymbolAddress((void**)&p_w1_h, g_w1_h);
    cudaGetSymbolAddress((void**)&p_w2_h, g_w2_h);
    cudaGetSymbolAddress((void**)&p_rel_h, g_rel_h);

    cudaFuncSetAttribute((const void*)mma_gemm_h<false, false>,
                         cudaFuncAttributeMaxDynamicSharedMemorySize, GEMM_SMEM_BYTES);
    cudaFuncSetAttribute((const void*)mma_gemm_h<true, true>,
                         cudaFuncAttributeMaxDynamicSharedMemorySize, GEMM_SMEM_BYTES);
    cudaFuncSetAttribute((const void*)mma_gemm_qkv,
                         cudaFuncAttributeMaxDynamicSharedMemorySize, GEMM_SMEM_BYTES);

    // 0. batched fp32->fp16 conversions (one launch)
    {
        CvtArgs a;
        const float* srcs[NSEG] = {Wq, Wk, Wv, Wo, W1, W2, rel_tab};
        __half* dsts[NSEG] = {p_wq_h, p_wk_h, p_wv_h, p_wo_h, p_w1_h, p_w2_h, p_rel_h};
        int ns[NSEG] = {D_ * D_, D_ * D_, D_ * D_, D_ * D_, D_ * DF_, DF_ * D_, R_ * D_};
        int cum = 0;
        for (int i = 0; i < NSEG; i++) {
            a.src[i] = srcs[i]; a.dst[i] = dsts[i]; a.n[i] = ns[i];
            a.cum[i] = cum;
            cum += (ns[i] + 2047) / 2048;
        }
        cvt_f2h_multi<<<cum, 256>>>(a);
    }

    // 1. ln0
    ln_dual_kernel<<<M_, 256>>>(hidden, ln0g, ln0b, p_hsnorm, p_hsnorm_h);

    // 2. fused Q,K,V GEMMs -> fp16 outputs (tile 128x128)
    QKVArgs qkv;
    qkv.Bm[0] = p_wq_h; qkv.Bm[1] = p_wk_h; qkv.Bm[2] = p_wv_h;
    qkv.bias[0] = bq; qkv.bias[1] = nullptr; qkv.bias[2] = nullptr;
    qkv.C[0] = p_q_h; qkv.C[1] = p_k_h; qkv.C[2] = p_v_h;
    dim3 gQKV(D_ / 128, M_ / 128, 3);
    mma_gemm_qkv<<<gQKV, 256, GEMM_SMEM_BYTES>>>(p_hsnorm_h, qkv, M_, D_, D_);

    // 3. edge scores
    score_kernel<<<(B_ * E_) / 4, dim3(32, 4)>>>(p_q_h, p_k_h, p_rel_h, esrc, edst, erel, p_score);

    // 4. deterministic binning by dst
    zero_cnt_kernel<<<(B_ * L_) / 256, 256>>>();
    hist_kernel<<<(B_ * E_) / 256, 256>>>(edst);
    scan_kernel<<<B_, L_>>>();
    fill_block_kernel<<<512, 256>>>(edst);

    // 5. aggregation -> o_h (fp16)
    agg_kernel<<<dim3(L_, B_), 256>>>(p_v_h, p_rel_h, esrc, erel, p_score);

    // 6. t1 = hs_norm + o @ Wo + bo ; ln1 -> out (dual)
    dim3 gD(D_ / 128, M_ / 128);
    mma_gemm_h<false, false><<<gD, 256, GEMM_SMEM_BYTES>>>(
        p_o_h, p_wo_h, bo, p_hsnorm, p_t1, nullptr, M_, D_, D_);
    ln_dual_kernel<<<M_, 256>>>(p_t1, ln1g, ln1b, p_out, p_out_h);

    // 7. FFN
    dim3 gDF(DF_ / 128, M_ / 128);
    mma_gemm_h<true, true><<<gDF, 256, GEMM_SMEM_BYTES>>>(
        p_out_h, p_w1_h, b1, nullptr, nullptr, p_h1_h, M_, DF_, D_);
    mma_gemm_h<false, false><<<gD, 256, GEMM_SMEM_BYTES>>>(
        p_h1_h, p_w2_h, b2, p_out, p_f, nullptr, M_, D_, DF_);

    // 8. final
    ln_elu_res_kernel<<<M_, 256>>>(p_f, ln2g, ln2b, hidden, out);
}

// round 8
// speedup vs baseline: 2.0010x; 1.0700x over previous
#include <cuda_runtime.h>
#include <cuda_fp16.h>
#include <math.h>

// Problem constants
#define B_  4
#define L_  1024
#define D_  1024
#define DF_ 4096
#define E_  32768
#define R_  64
#define M_  (B_ * L_)
#define EPS_ 1e-6f

// ---------------------------------------------------------------------------
// Scratch
// ---------------------------------------------------------------------------
__device__ float  g_hsnorm[M_ * D_];
__device__ __half g_hsnorm_h[M_ * D_];
__device__ __half g_q_h[M_ * D_];
__device__ __half g_k_h[M_ * D_];
__device__ __half g_v_h[M_ * D_];
__device__ __half g_o_h[M_ * D_];
__device__ float  g_t1[M_ * D_];
__device__ float  g_out[M_ * D_];
__device__ __half g_out_h[M_ * D_];
__device__ __half g_h1_h[M_ * DF_];
__device__ float  g_f[M_ * D_];
__device__ float  g_score[B_ * E_];
__device__ int    g_perm[B_ * E_];
__device__ int    g_cnt[B_ * L_];
__device__ int    g_off[B_ * (L_ + 1)];
// edge-phase algebra buffers
__device__ float  g_T[M_ * R_];        // T[d,r] = q[d] . rel[r]
__device__ float  g_term1[M_ * D_];    // (sum s*v)/z   (fp32)
__device__ float  g_z[M_];             // per-dst score sum
__device__ __half g_wn_h[M_ * R_];     // per-dst per-rel score sums / z
// fp16 weights + tables
__device__ __half g_wq_h[D_ * D_];
__device__ __half g_wk_h[D_ * D_];
__device__ __half g_wv_h[D_ * D_];
__device__ __half g_wo_h[D_ * D_];
__device__ __half g_w1_h[D_ * DF_];
__device__ __half g_w2_h[DF_ * D_];
__device__ __half g_rel_h[R_ * D_];
__device__ __half g_rel_t_h[D_ * R_];  // transposed rel table (k-major)

// ---------------------------------------------------------------------------
// Batched fp32 -> fp16 convert: 7 segments, one launch
// ---------------------------------------------------------------------------
#define NSEG 7
struct CvtArgs {
    const float* src[NSEG];
    __half* dst[NSEG];
    int n[NSEG];
    int cum[NSEG];
};

__global__ void cvt_f2h_multi(CvtArgs a) {
    int blk = blockIdx.x;
    int seg = 0;
    #pragma unroll
    for (int i = 1; i < NSEG; i++) if (blk >= a.cum[i]) seg = i;
    int i = ((blk - a.cum[seg]) * 256 + threadIdx.x) * 8;
    if (i >= a.n[seg]) return;
    const float* x = a.src[seg];
    float4 v0 = *(const float4*)(x + i);
    float4 v1 = *(const float4*)(x + i + 4);
    __half2 h[4];
    h[0] = __floats2half2_rn(v0.x, v0.y);
    h[1] = __floats2half2_rn(v0.z, v0.w);
    h[2] = __floats2half2_rn(v1.x, v1.y);
    h[3] = __floats2half2_rn(v1.z, v1.w);
    *(uint4*)(a.dst[seg] + i) = *(uint4*)h;
}

// rel_table transpose -> fp16 k-major [D, R]
__global__ void rel_transpose(const float* __restrict__ rel) {
    int idx = blockIdx.x * 256 + threadIdx.x;   // 0..65535
    int k = idx >> 6, n = idx & 63;
    g_rel_t_h[idx] = __float2half(rel[n * D_ + k]);
}

// ---------------------------------------------------------------------------
// LayerNorm helpers
// ---------------------------------------------------------------------------
__device__ __forceinline__ void row_moments(float4 v, float& mean, float& rstd,
                                            float* sh1, float* sh2) {
    float s  = v.x + v.y + v.z + v.w;
    float sq = v.x * v.x + v.y * v.y + v.z * v.z + v.w * v.w;
    #pragma unroll
    for (int o = 16; o; o >>= 1) {
        s  += __shfl_xor_sync(0xffffffffu, s, o);
        sq += __shfl_xor_sync(0xffffffffu, sq, o);
    }
    int warp = threadIdx.x >> 5, lane = threadIdx.x & 31;
    if (lane == 0) { sh1[warp] = s; sh2[warp] = sq; }
    __syncthreads();
    if (threadIdx.x < 8) {
        s = sh1[threadIdx.x]; sq = sh2[threadIdx.x];
        #pragma unroll
        for (int o = 4; o; o >>= 1) {
            s  += __shfl_xor_sync(0xffu, s, o);
            sq += __shfl_xor_sync(0xffu, sq, o);
        }
        if (threadIdx.x == 0) { sh1[0] = s; sh2[0] = sq; }
    }
    __syncthreads();
    mean = sh1[0] * (1.0f / D_);
    float var = sh2[0] * (1.0f / D_) - mean * mean;
    rstd = rsqrtf(var + EPS_);
}

__global__ void ln_dual_kernel(const float* __restrict__ x, const float* __restrict__ g,
                               const float* __restrict__ b, float* __restrict__ y,
                               __half* y16) {
    __shared__ float sh1[8], sh2[8];
    size_t row = blockIdx.x;
    int t = threadIdx.x;
    float4 v = ((const float4*)(x + row * D_))[t];
    float mean, rstd;
    row_moments(v, mean, rstd, sh1, sh2);
    float4 gv = ((const float4*)g)[t];
    float4 bv = ((const float4*)b)[t];
    float4 o;
    o.x = (v.x - mean) * rstd * gv.x + bv.x;
    o.y = (v.y - mean) * rstd * gv.y + bv.y;
    o.z = (v.z - mean) * rstd * gv.z + bv.z;
    o.w = (v.w - mean) * rstd * gv.w + bv.w;
    ((float4*)(y + row * D_))[t] = o;
    if (y16) {
        __half2 h0 = __floats2half2_rn(o.x, o.y);
        __half2 h1 = __floats2half2_rn(o.z, o.w);
        __half2* p = (__half2*)(y16 + row * D_);
        p[2 * t] = h0; p[2 * t + 1] = h1;
    }
}

__global__ void ln_elu_res_kernel(const float* __restrict__ x, const float* __restrict__ g,
                                  const float* __restrict__ b,
                                  const float* __restrict__ hidden,
                                  float* __restrict__ out) {
    __shared__ float sh1[8], sh2[8];
    size_t row = blockIdx.x;
    int t = threadIdx.x;
    float4 v = ((const float4*)(x + row * D_))[t];
    float mean, rstd;
    row_moments(v, mean, rstd, sh1, sh2);
    float4 gv = ((const float4*)g)[t];
    float4 bv = ((const float4*)b)[t];
    float4 hv = ((const float4*)(hidden + row * D_))[t];
    float n0 = (v.x - mean) * rstd * gv.x + bv.x;
    float n1 = (v.y - mean) * rstd * gv.y + bv.y;
    float n2 = (v.z - mean) * rstd * gv.z + bv.z;
    float n3 = (v.w - mean) * rstd * gv.w + bv.w;
    float4 o;
    o.x = hv.x + (n0 > 0.f ? n0 : expm1f(n0));
    o.y = hv.y + (n1 > 0.f ? n1 : expm1f(n1));
    o.z = hv.z + (n2 > 0.f ? n2 : expm1f(n2));
    o.w = hv.w + (n3 > 0.f ? n3 : expm1f(n3));
    ((float4*)(out + row * D_))[t] = o;
}

// ---------------------------------------------------------------------------
// FP16 tensor-core GEMM: CTA 128x128, 8 warps (2x4), warp 64x32, BK=32,
// 3-stage cp.async, 2 CTAs/SM, ldmatrix for BOTH A and B fragments.
// ---------------------------------------------------------------------------
__device__ __forceinline__ void mma_f16(float* c, const unsigned* a, const unsigned* b) {
    asm volatile(
        "mma.sync.aligned.m16n8k16.row.col.f32.f16.f16.f32 "
        "{%0,%1,%2,%3}, {%4,%5,%6,%7}, {%8,%9}, {%0,%1,%2,%3};"
        : "+f"(c[0]), "+f"(c[1]), "+f"(c[2]), "+f"(c[3])
        : "r"(a[0]), "r"(a[1]), "r"(a[2]), "r"(a[3]), "r"(b[0]), "r"(b[1]));
}

#define CP16(dst, src) \
    asm volatile("cp.async.cg.shared.global [%0], [%1], 16;\n" :: "r"(dst), "l"(src))

#define APW   20                     // A pitch, 32-bit words (40 halves)
#define ASTG  (128 * APW)            // 2560 words / stage
#define PBHN  136                    // B pitch in fp16 (272 B, ≡16 mod 128)
#define BSTGW (32 * PBHN / 2)        // 2176 words / stage
#define NSTAGE 3
#define GEMM_SMEM_BYTES (NSTAGE * (ASTG + BSTGW) * 4)   // 56832

template <bool RELU, bool OUTHALF>
__device__ __forceinline__ void gemm_body_h(
    unsigned* sm, const __half* __restrict__ A, const __half* __restrict__ Bm,
    const float* bias, const float* res, float* C32, __half* C16,
    int N, int K, int bm, int bn) {
    unsigned* As = sm;
    unsigned* Bs = sm + NSTAGE * ASTG;
    int tid = threadIdx.x;
    int warp = tid >> 5, lane = tid & 31;
    int g = lane >> 2, tg = lane & 3;
    int wm = (warp & 1) * 64, wn = (warp >> 1) * 32;

    int arow = tid >> 1;
    const __half* aptr = A + (size_t)(bm + arow) * K + (tid & 1) * 16;
    unsigned a_dst = (unsigned)__cvta_generic_to_shared(As + arow * APW + (tid & 1) * 8);
    int brow = tid >> 3, bc = (tid & 7) * 16;
    const __half* bptr = Bm + (size_t)brow * N + bn + bc;
    unsigned b_dst = (unsigned)__cvta_generic_to_shared((__half*)Bs + brow * PBHN + bc);

    // ldmatrix lane bases
    int quad = lane >> 3, j = lane & 7;
    int lrow = (quad & 1) * 8 + j;
    int lcol = wn + (quad >> 1) * 8;
    unsigned b_frag_base = (unsigned)__cvta_generic_to_shared((__half*)Bs + lrow * PBHN + lcol);
    // A: row = (quad&1)*8 + j (within 16-row tile), col = (quad>>1)*8 halves
    unsigned a_frag_base = (unsigned)__cvta_generic_to_shared(
        (__half*)As + lrow * (APW * 2) + (quad >> 1) * 8);

    int ntiles = K >> 5;

    #pragma unroll
    for (int s = 0; s < NSTAGE - 1; s++) {
        const __half* ap = aptr + s * 32;
        const __half* bp = bptr + (size_t)s * 32 * N;
        unsigned ad = a_dst + s * ASTG * 4;
        unsigned bd = b_dst + s * BSTGW * 4;
        CP16(ad, ap); CP16(ad + 16, ap + 8);
        CP16(bd, bp); CP16(bd + 16, bp + 8);
        asm volatile("cp.async.commit_group;\n");
    }

    float acc[4][4][4];
    #pragma unroll
    for (int mt = 0; mt < 4; mt++)
        #pragma unroll
        for (int nt = 0; nt < 4; nt++)
            #pragma unroll
            for (int r = 0; r < 4; r++) acc[mt][nt][r] = 0.f;

    for (int kt = 0; kt < ntiles; kt++) {
        asm volatile("cp.async.wait_group %0;\n" :: "n"(NSTAGE - 2));
        __syncthreads();

        int nx = kt + NSTAGE - 1;
        if (nx < ntiles) {
            int st = nx % NSTAGE;
            const __half* ap = aptr + nx * 32;
            const __half* bp = bptr + (size_t)nx * 32 * N;
            unsigned ad = a_dst + st * ASTG * 4;
            unsigned bd = b_dst + st * BSTGW * 4;
            CP16(ad, ap); CP16(ad + 16, ap + 8);
            CP16(bd, bp); CP16(bd + 16, bp + 8);
        }
        asm volatile("cp.async.commit_group;\n");

        int cur = kt % NSTAGE;
        unsigned asm_base = a_frag_base + cur * ASTG * 4 + wm * APW * 4;
        unsigned bsm = b_frag_base + cur * BSTGW * 4;
        #pragma unroll
        for (int ks = 0; ks < 2; ks++) {
            unsigned af[4][4];
            #pragma unroll
            for (int mt = 0; mt < 4; mt++) {
                unsigned aaddr = asm_base + mt * 16 * APW * 4 + ks * 32;
                asm volatile(
                    "ldmatrix.sync.aligned.m8n8.x4.shared.b16 {%0,%1,%2,%3}, [%4];"
                    : "=r"(af[mt][0]), "=r"(af[mt][1]), "=r"(af[mt][2]), "=r"(af[mt][3])
                    : "r"(aaddr));
            }
            unsigned bf[4][2];
            #pragma unroll
            for (int nb = 0; nb < 2; nb++) {
                unsigned addr = bsm + ks * 16 * (PBHN * 2) + nb * 32;
                asm volatile(
                    "ldmatrix.sync.aligned.m8n8.x4.trans.shared.b16 {%0,%1,%2,%3}, [%4];"
                    : "=r"(bf[2 * nb][0]), "=r"(bf[2 * nb][1]),
                      "=r"(bf[2 * nb + 1][0]), "=r"(bf[2 * nb + 1][1])
                    : "r"(addr));
            }
            #pragma unroll
            for (int mt = 0; mt < 4; mt++)
                #pragma unroll
                for (int nt = 0; nt < 4; nt++)
                    mma_f16(acc[mt][nt], af[mt], bf[nt]);
        }
    }

    #pragma unroll
    for (int mt = 0; mt < 4; mt++) {
        #pragma unroll
        for (int nt = 0; nt < 4; nt++) {
            int col = bn + wn + nt * 8 + tg * 2;
            #pragma unroll
            for (int h = 0; h < 2; h++) {
                int row = bm + wm + mt * 16 + g + h * 8;
                float vx = acc[mt][nt][2 * h];
                float vy = acc[mt][nt][2 * h + 1];
                if (bias) {
                    float2 bb = *(const float2*)(bias + col);
                    vx += bb.x; vy += bb.y;
                }
                if (res) {
                    float2 rr = *(const float2*)(res + (size_t)row * N + col);
                    vx += rr.x; vy += rr.y;
                }
                if (RELU) { vx = fmaxf(vx, 0.f); vy = fmaxf(vy, 0.f); }
                if (OUTHALF)
                    *(__half2*)(C16 + (size_t)row * N + col) = __floats2half2_rn(vx, vy);
                else
                    *(float2*)(C32 + (size_t)row * N + col) = make_float2(vx, vy);
            }
        }
    }
}

template <bool RELU, bool OUTHALF>
__global__ __launch_bounds__(256, 2) void mma_gemm_h(
    const __half* __restrict__ A, const __half* __restrict__ Bm,
    const float* bias, const float* res, float* C32, __half* C16,
    int M, int N, int K) {
    extern __shared__ unsigned sm[];
    gemm_body_h<RELU, OUTHALF>(sm, A, Bm, bias, res, C32, C16, N, K,
                               blockIdx.y * 128, blockIdx.x * 128);
}

struct QKVArgs {
    const __half* Bm[3];
    const float* bias[3];
    __half* C[3];
};

__global__ __launch_bounds__(256, 2) void mma_gemm_qkv(
    const __half* __restrict__ A, QKVArgs args, int M, int N, int K) {
    extern __shared__ unsigned sm[];
    int z = blockIdx.z;
    gemm_body_h<false, true>(sm, A, args.Bm[z], args.bias[z], nullptr, nullptr,
                             args.C[z], N, K, blockIdx.y * 128, blockIdx.x * 128);
}

// ---------------------------------------------------------------------------
// Small-N GEMM: T[M,64] = q[M,1024] @ rel_t[1024,64]  (fp32 out)
// CTA 128x64, 8 warps (4m x 2n), warp 32x32, BK=32.
// ---------------------------------------------------------------------------
#define PB64 72                       // B pitch halves (144 B, ≡16 mod 128)
#define BSTG64 (32 * PB64 / 2)        // 1152 words / stage

__global__ __launch_bounds__(256, 2) void gemm_T64(
    const __half* __restrict__ A, const __half* __restrict__ Bm,
    float* __restrict__ C, int K) {
    __shared__ unsigned smT[NSTAGE * (ASTG + BSTG64)];
    unsigned* As = smT;
    unsigned* Bs = smT + NSTAGE * ASTG;
    const int N = R_;
    int tid = threadIdx.x;
    int warp = tid >> 5, lane = tid & 31;
    int g = lane >> 2, tg = lane & 3;
    int wm = (warp & 3) * 32, wn = (warp >> 2) * 32;
    int bm = blockIdx.y * 128;

    int arow = tid >> 1;
    const __half* aptr = A + (size_t)(bm + arow) * K + (tid & 1) * 16;
    unsigned a_dst = (unsigned)__cvta_generic_to_shared(As + arow * APW + (tid & 1) * 8);
    int brow = tid >> 3, bc = (tid & 7) * 8;
    const __half* bptr = Bm + (size_t)brow * N + bc;
    unsigned b_dst = (unsigned)__cvta_generic_to_shared((__half*)Bs + brow * PB64 + bc);

    int quad = lane >> 3, j = lane & 7;
    int lrow = (quad & 1) * 8 + j;
    int lcol = wn + (quad >> 1) * 8;
    unsigned b_frag_base = (unsigned)__cvta_generic_to_shared((__half*)Bs + lrow * PB64 + lcol);

    int ntiles = K >> 5;
    #pragma unroll
    for (int s = 0; s < NSTAGE - 1; s++) {
        unsigned ad = a_dst + s * ASTG * 4;
        unsigned bd = b_dst + s * BSTG64 * 4;
        CP16(ad, aptr + s * 32); CP16(ad + 16, aptr + s * 32 + 8);
        CP16(bd, bptr + (size_t)s * 32 * N);
        asm volatile("cp.async.commit_group;\n");
    }

    float acc[2][4][4];
    #pragma unroll
    for (int mt = 0; mt < 2; mt++)
        #pragma unroll
        for (int nt = 0; nt < 4; nt++)
            #pragma unroll
            for (int r = 0; r < 4; r++) acc[mt][nt][r] = 0.f;

    for (int kt = 0; kt < ntiles; kt++) {
        asm volatile("cp.async.wait_group %0;\n" :: "n"(NSTAGE - 2));
        __syncthreads();
        int nx = kt + NSTAGE - 1;
        if (nx < ntiles) {
            int st = nx % NSTAGE;
            unsigned ad = a_dst + st * ASTG * 4;
            unsigned bd = b_dst + st * BSTG64 * 4;
            CP16(ad, aptr + nx * 32); CP16(ad + 16, aptr + nx * 32 + 8);
            CP16(bd, bptr + (size_t)nx * 32 * N);
        }
        asm volatile("cp.async.commit_group;\n");

        int cur = kt % NSTAGE;
        const unsigned* Ab = As + cur * ASTG;
        unsigned bsm = b_frag_base + cur * BSTG64 * 4;
        #pragma unroll
        for (int ks = 0; ks < 2; ks++) {
            unsigned af[2][4];
            #pragma unroll
            for (int mt = 0; mt < 2; mt++) {
                const unsigned* p = Ab + (wm + mt * 16 + g) * APW + ks * 8 + tg;
                af[mt][0] = p[0];
                af[mt][1] = p[8 * APW];
                af[mt][2] = p[4];
                af[mt][3] = p[8 * APW + 4];
            }
            unsigned bf[4][2];
            #pragma unroll
            for (int nb = 0; nb < 2; nb++) {
                unsigned addr = bsm + ks * 16 * (PB64 * 2) + nb * 32;
                asm volatile(
                    "ldmatrix.sync.aligned.m8n8.x4.trans.shared.b16 {%0,%1,%2,%3}, [%4];"
                    : "=r"(bf[2 * nb][0]), "=r"(bf[2 * nb][1]),
                      "=r"(bf[2 * nb + 1][0]), "=r"(bf[2 * nb + 1][1])
                    : "r"(addr));
            }
            #pragma unroll
            for (int mt = 0; mt < 2; mt++)
                #pragma unroll
                for (int nt = 0; nt < 4; nt++)
                    mma_f16(acc[mt][nt], af[mt], bf[nt]);
        }
    }

    #pragma unroll
    for (int mt = 0; mt < 2; mt++)
        #pragma unroll
        for (int nt = 0; nt < 4; nt++) {
            int col = wn + nt * 8 + tg * 2;
            #pragma unroll
            for (int h = 0; h < 2; h++) {
                int row = bm + wm + mt * 16 + g + h * 8;
                *(float2*)(C + (size_t)row * N + col) =
                    make_float2(acc[mt][nt][2 * h], acc[mt][nt][2 * h + 1]);
            }
        }
}

// ---------------------------------------------------------------------------
// Edge scores: k[src].q[dst] (2 fp16 rows) + T[dst,rel]
// ---------------------------------------------------------------------------
__global__ void score_kernel(const __half* __restrict__ Q, const __half* __restrict__ Km,
                             const float* __restrict__ T,
                             const int* __restrict__ src, const int* __restrict__ dst,
                             const int* __restrict__ rel, float* __restrict__ score) {
    int idx = blockIdx.x * 4 + threadIdx.y;
    int b = idx >> 15;
    int lane = threadIdx.x;
    int s = src[idx], d = dst[idx], r = rel[idx];
    const __half* kr = Km + ((size_t)b * L_ + s) * D_;
    const __half* qr = Q + ((size_t)b * L_ + d) * D_;
    float acc = 0.f;
    #pragma unroll
    for (int i = 0; i < 4; i++) {
        int c = (lane + 32 * i) * 8;
        uint4 kv = *(const uint4*)(kr + c);
        uint4 qv = *(const uint4*)(qr + c);
        const __half2* kh = (const __half2*)&kv;
        const __half2* qh = (const __half2*)&qv;
        #pragma unroll
        for (int j = 0; j < 4; j++) {
            float2 kf = __half22float2(kh[j]);
            float2 qf = __half22float2(qh[j]);
            acc = fmaf(kf.x, qf.x, acc);
            acc = fmaf(kf.y, qf.y, acc);
        }
    }
    #pragma unroll
    for (int o = 16; o; o >>= 1) acc += __shfl_xor_sync(0xffffffffu, acc, o);
    if (lane == 0) {
        float sc = (acc + T[((size_t)b * L_ + d) * R_ + r]) * 0.03125f;
        sc = fminf(fmaxf(sc, -10.f), 10.f);
        score[idx] = expf(sc);
    }
}

// ---------------------------------------------------------------------------
// Deterministic binning
// ---------------------------------------------------------------------------
__global__ void zero_cnt_kernel() {
    int i = blockIdx.x * 256 + threadIdx.x;
    if (i < B_ * L_) g_cnt[i] = 0;
}

__global__ void hist_kernel(const int* __restrict__ edge_dst) {
    int idx = blockIdx.x * 256 + threadIdx.x;
    if (idx < B_ * E_) atomicAdd(&g_cnt[(idx >> 15) * L_ + edge_dst[idx]], 1);
}

__global__ void scan_kernel() {
    int b = blockIdx.x, t = threadIdx.x;
    __shared__ int s[L_];
    int c = g_cnt[b * L_ + t];
    s[t] = c;
    __syncthreads();
    for (int off = 1; off < L_; off <<= 1) {
        int v = (t >= off) ? s[t - off] : 0;
        __syncthreads();
        s[t] += v;
        __syncthreads();
    }
    g_off[b * (L_ + 1) + t] = s[t] - c;
    if (t == L_ - 1) g_off[b * (L_ + 1) + L_] = s[t];
}

__global__ void fill_block_kernel(const int* __restrict__ edge_dst) {
    __shared__ int sd[1024];
    int b = blockIdx.x >> 7;
    int nodebase = (blockIdx.x & 127) * 8;
    int warp = threadIdx.x >> 5, lane = threadIdx.x & 31;
    int node = nodebase + warp;
    int w = g_off[b * (L_ + 1) + node];
    int* pb = g_perm + b * E_;
    const int* dv = edge_dst + b * E_;
    for (int base = 0; base < E_; base += 1024) {
        __syncthreads();
        #pragma unroll
        for (int i = 0; i < 4; i++) sd[threadIdx.x + 256 * i] = dv[base + threadIdx.x + 256 * i];
        __syncthreads();
        for (int c = 0; c < 1024; c += 32) {
            int d = sd[c + lane];
            unsigned m = __ballot_sync(0xffffffffu, d == node);
            if (d == node) pb[w + __popc(m & ((1u << lane) - 1))] = base + c + lane;
            w += __popc(m);
        }
    }
}

// ---------------------------------------------------------------------------
// agg1: term1n = (sum s*v[src]) / z  (fp32), and z per dst
// ---------------------------------------------------------------------------
__global__ void agg1_kernel(const __half* __restrict__ V,
                            const int* __restrict__ src,
                            const float* __restrict__ score) {
    int node = blockIdx.x, b = blockIdx.y;
    int t = threadIdx.x;
    int beg = g_off[b * (L_ + 1) + node];
    int end = g_off[b * (L_ + 1) + node + 1];
    const int* pb = g_perm + b * E_;
    float4 acc = make_float4(0.f, 0.f, 0.f, 0.f);
    float z = 0.f;
    for (int i = beg; i < end; i++) {
        int e = pb[i];
        float s = score[b * E_ + e];
        int sn = src[b * E_ + e];
        uint2 vw = *(const uint2*)(V + ((size_t)b * L_ + sn) * D_ + 4 * t);
        const __half2* vh = (const __half2*)&vw;
        float2 v0 = __half22float2(vh[0]), v1 = __half22float2(vh[1]);
        acc.x = fmaf(s, v0.x, acc.x);
        acc.y = fmaf(s, v0.y, acc.y);
        acc.z = fmaf(s, v1.x, acc.z);
        acc.w = fmaf(s, v1.y, acc.w);
        z += s;
    }
    float inv = 1.0f / z;
    *(float4*)(g_term1 + ((size_t)b * L_ + node) * D_ + 4 * t) =
        make_float4(acc.x * inv, acc.y * inv, acc.z * inv, acc.w * inv);
    if (t == 0) g_z[b * L_ + node] = z;
}

// ---------------------------------------------------------------------------
// Wn: per-dst per-rel score sums / z -> fp16 [M, 64]. Thread t owns rel t.
// ---------------------------------------------------------------------------
__global__ void wn_kernel(const int* __restrict__ rel, const float* __restrict__ score) {
    int node = blockIdx.x, b = blockIdx.y;
    int t = threadIdx.x;   // 0..63
    int beg = g_off[b * (L_ + 1) + node];
    int end = g_off[b * (L_ + 1) + node + 1];
    const int* pb = g_perm + b * E_;
    float W = 0.f;
    for (int i = beg; i < end; i++) {
        int e = pb[i];
        float s = score[b * E_ + e];
        int r = rel[b * E_ + e];
        if (r == t) W += s;
    }
    float z = g_z[b * L_ + node];
    g_wn_h[((size_t)b * L_ + node) * R_ + t] = __float2half(W / z);
}

// ---------------------------------------------------------------------------
// Launch
// ---------------------------------------------------------------------------
extern "C" void kernel_launch(void* const* d_in, const int* in_sizes, int n_in,
                              void* d_out, int out_size) {
    const float* hidden  = (const float*)d_in[0];
    const float* rel_tab = (const float*)d_in[1];
    const float* Wq = (const float*)d_in[2];
    const float* bq = (const float*)d_in[3];
    const float* Wk = (const float*)d_in[4];
    const float* Wv = (const float*)d_in[5];
    const float* Wo = (const float*)d_in[6];
    const float* bo = (const float*)d_in[7];
    const float* ln0g = (const float*)d_in[8];
    const float* ln0b = (const float*)d_in[9];
    const float* ln1g = (const float*)d_in[10];
    const float* ln1b = (const float*)d_in[11];
    const float* W1 = (const float*)d_in[12];
    const float* b1 = (const float*)d_in[13];
    const float* W2 = (const float*)d_in[14];
    const float* b2 = (const float*)d_in[15];
    const float* ln2g = (const float*)d_in[16];
    const float* ln2b = (const float*)d_in[17];
    const int* esrc = (const int*)d_in[18];
    const int* edst = (const int*)d_in[19];
    const int* erel = (const int*)d_in[20];
    float* out = (float*)d_out;

    float *p_hsnorm, *p_t1, *p_out, *p_f, *p_score, *p_T, *p_term1;
    __half *p_hsnorm_h, *p_q_h, *p_k_h, *p_v_h, *p_o_h, *p_out_h, *p_h1_h, *p_wn_h;
    __half *p_wq_h, *p_wk_h, *p_wv_h, *p_wo_h, *p_w1_h, *p_w2_h, *p_rel_h, *p_rel_t_h;
    cudaGetSymbolAddress((void**)&p_hsnorm, g_hsnorm);
    cudaGetSymbolAddress((void**)&p_hsnorm_h, g_hsnorm_h);
    cudaGetSymbolAddress((void**)&p_q_h, g_q_h);
    cudaGetSymbolAddress((void**)&p_k_h, g_k_h);
    cudaGetSymbolAddress((void**)&p_v_h, g_v_h);
    cudaGetSymbolAddress((void**)&p_o_h, g_o_h);
    cudaGetSymbolAddress((void**)&p_t1, g_t1);
    cudaGetSymbolAddress((void**)&p_out, g_out);
    cudaGetSymbolAddress((void**)&p_out_h, g_out_h);
    cudaGetSymbolAddress((void**)&p_h1_h, g_h1_h);
    cudaGetSymbolAddress((void**)&p_f, g_f);
    cudaGetSymbolAddress((void**)&p_score, g_score);
    cudaGetSymbolAddress((void**)&p_T, g_T);
    cudaGetSymbolAddress((void**)&p_term1, g_term1);
    cudaGetSymbolAddress((void**)&p_wn_h, g_wn_h);
    cudaGetSymbolAddress((void**)&p_wq_h, g_wq_h);
    cudaGetSymbolAddress((void**)&p_wk_h, g_wk_h);
    cudaGetSymbolAddress((void**)&p_wv_h, g_wv_h);
    cudaGetSymbolAddress((void**)&p_wo_h, g_wo_h);
    cudaGetSymbolAddress((void**)&p_w1_h, g_w1_h);
    cudaGetSymbolAddress((void**)&p_w2_h, g_w2_h);
    cudaGetSymbolAddress((void**)&p_rel_h, g_rel_h);
    cudaGetSymbolAddress((void**)&p_rel_t_h, g_rel_t_h);

    cudaFuncSetAttribute((const void*)mma_gemm_h<false, false>,
                         cudaFuncAttributeMaxDynamicSharedMemorySize, GEMM_SMEM_BYTES);
    cudaFuncSetAttribute((const void*)mma_gemm_h<false, true>,
                         cudaFuncAttributeMaxDynamicSharedMemorySize, GEMM_SMEM_BYTES);
    cudaFuncSetAttribute((const void*)mma_gemm_h<true, true>,
                         cudaFuncAttributeMaxDynamicSharedMemorySize, GEMM_SMEM_BYTES);
    cudaFuncSetAttribute((const void*)mma_gemm_qkv,
                         cudaFuncAttributeMaxDynamicSharedMemorySize, GEMM_SMEM_BYTES);

    // 0. conversions
    {
        CvtArgs a;
        const float* srcs[NSEG] = {Wq, Wk, Wv, Wo, W1, W2, rel_tab};
        __half* dsts[NSEG] = {p_wq_h, p_wk_h, p_wv_h, p_wo_h, p_w1_h, p_w2_h, p_rel_h};
        int ns[NSEG] = {D_ * D_, D_ * D_, D_ * D_, D_ * D_, D_ * DF_, DF_ * D_, R_ * D_};
        int cum = 0;
        for (int i = 0; i < NSEG; i++) {
            a.src[i] = srcs[i]; a.dst[i] = dsts[i]; a.n[i] = ns[i];
            a.cum[i] = cum;
            cum += (ns[i] + 2047) / 2048;
        }
        cvt_f2h_multi<<<cum, 256>>>(a);
    }
    rel_transpose<<<(D_ * R_) / 256, 256>>>(rel_tab);

    // 1. ln0
    ln_dual_kernel<<<M_, 256>>>(hidden, ln0g, ln0b, p_hsnorm, p_hsnorm_h);

    // 2. fused Q,K,V GEMMs
    QKVArgs qkv;
    qkv.Bm[0] = p_wq_h; qkv.Bm[1] = p_wk_h; qkv.Bm[2] = p_wv_h;
    qkv.bias[0] = bq; qkv.bias[1] = nullptr; qkv.bias[2] = nullptr;
    qkv.C[0] = p_q_h; qkv.C[1] = p_k_h; qkv.C[2] = p_v_h;
    dim3 gQKV(D_ / 128, M_ / 128, 3);
    mma_gemm_qkv<<<gQKV, 256, GEMM_SMEM_BYTES>>>(p_hsnorm_h, qkv, M_, D_, D_);

    // 3. T = q @ rel^T  [M, 64]
    gemm_T64<<<dim3(1, M_ / 128), 256>>>(p_q_h, p_rel_t_h, p_T, D_);

    // 4. edge scores (2-row gathers + T lookup)
    score_kernel<<<(B_ * E_) / 4, dim3(32, 4)>>>(p_q_h, p_k_h, p_T, esrc, edst, erel, p_score);

    // 5. deterministic binning by dst
    zero_cnt_kernel<<<(B_ * L_) / 256, 256>>>();
    hist_kernel<<<(B_ * E_) / 256, 256>>>(edst);
    scan_kernel<<<B_, L_>>>();
    fill_block_kernel<<<512, 256>>>(edst);

    // 6. agg1 (v-only gathers) + Wn histogram
    agg1_kernel<<<dim3(L_, B_), 256>>>(p_v_h, esrc, p_score);
    wn_kernel<<<dim3(L_, B_), 64>>>(erel, p_score);

    // 7. o = Wn @ rel + term1n  -> fp16  (K=64 GEMM)
    dim3 gD(D_ / 128, M_ / 128);
    mma_gemm_h<false, true><<<gD, 256, GEMM_SMEM_BYTES>>>(
        p_wn_h, p_rel_h, nullptr, p_term1, nullptr, p_o_h, M_, D_, R_);

    // 8. t1 = hs_norm + o @ Wo + bo ; ln1 -> out (dual)
    mma_gemm_h<false, false><<<gD, 256, GEMM_SMEM_BYTES>>>(
        p_o_h, p_wo_h, bo, p_hsnorm, p_t1, nullptr, M_, D_, D_);
    ln_dual_kernel<<<M_, 256>>>(p_t1, ln1g, ln1b, p_out, p_out_h);

    // 9. FFN
    dim3 gDF(DF_ / 128, M_ / 128);
    mma_gemm_h<true, true><<<gDF, 256, GEMM_SMEM_BYTES>>>(
        p_out_h, p_w1_h, b1, nullptr, nullptr, p_h1_h, M_, DF_, D_);
    mma_gemm_h<false, false><<<gD, 256, GEMM_SMEM_BYTES>>>(
        p_h1_h, p_w2_h, b2, p_out, p_f, nullptr, M_, D_, DF_);

    // 10. final
    ln_elu_res_kernel<<<M_, 256>>>(p_f, ln2g, ln2b, hidden, out);
}